// round 6
// baseline (speedup 1.0000x reference)
#include <cuda_runtime.h>
#include <cuda_bf16.h>
#include <cstdint>

// ---------------------------------------------------------------------------
// Problem constants
// ---------------------------------------------------------------------------
#define OUTF 4096
#define INF  11008
#define MDIM 4096                 // 2*2048 tokens
#define NDIM OUTF
#define KDIM INF
#define NVEC (OUTF * (INF / 8))   // 5,636,096 code vectors

// GEMM tiling
#define BM 128
#define BN 128
#define BK 32
#define KT (KDIM / BK)            // 344
#define MT (MDIM / BM)            // 32
#define NT (NDIM / BN)            // 32

#define TILE_G 8192               // packed gmem tile: 128 rows x 64B
#define SROW   80                 // padded smem row stride (conflict-free ldmatrix)
#define TILE_S (128 * SROW)       // 10240
#define NST 4
#define STAGE_BYTES (4 * TILE_S)  // 40960 (Ahi, Alo, Whi, Wlo)
#define SMEM_TOTAL (NST * STAGE_BYTES)   // 163840

// Packed bf16 operand tiles (static device arrays: alloc-guard safe)
__device__ __align__(256) uint8_t g_a_hi[(size_t)MT * KT * TILE_G];
__device__ __align__(256) uint8_t g_a_lo[(size_t)MT * KT * TILE_G];
__device__ __align__(256) uint8_t g_w_hi[(size_t)NT * KT * TILE_G];
__device__ __align__(256) uint8_t g_w_lo[(size_t)NT * KT * TILE_G];

// ---------------------------------------------------------------------------
// PTX helpers (all plain sm_80+ — compile at compute_103)
// ---------------------------------------------------------------------------
__device__ __forceinline__ uint32_t smem_u32(const void* p) {
    uint32_t a;
    asm("{ .reg .u64 t; cvta.to.shared.u64 t, %1; cvt.u32.u64 %0, t; }"
        : "=r"(a) : "l"(p));
    return a;
}

__device__ __forceinline__ void cp_async16(uint32_t sdst, const void* gsrc) {
    asm volatile("cp.async.cg.shared.global [%0], [%1], 16;"
                 :: "r"(sdst), "l"(gsrc) : "memory");
}
#define CP_COMMIT()  asm volatile("cp.async.commit_group;" ::: "memory")
#define CP_WAIT(n)   asm volatile("cp.async.wait_group %0;" :: "n"(n) : "memory")

__device__ __forceinline__ void ldsm4(uint32_t (&r)[4], uint32_t addr) {
    asm volatile("ldmatrix.sync.aligned.m8n8.x4.shared.b16 {%0,%1,%2,%3}, [%4];"
                 : "=r"(r[0]), "=r"(r[1]), "=r"(r[2]), "=r"(r[3]) : "r"(addr));
}

__device__ __forceinline__ void mma_bf16(float (&c)[4], const uint32_t (&a)[4],
                                         uint32_t b0, uint32_t b1) {
    asm volatile(
        "mma.sync.aligned.m16n8k16.row.col.f32.bf16.bf16.f32 "
        "{%0,%1,%2,%3}, {%4,%5,%6,%7}, {%8,%9}, {%0,%1,%2,%3};"
        : "+f"(c[0]), "+f"(c[1]), "+f"(c[2]), "+f"(c[3])
        : "r"(a[0]), "r"(a[1]), "r"(a[2]), "r"(a[3]), "r"(b0), "r"(b1));
}

// ---------------------------------------------------------------------------
// hi/lo bf16 split of 8 fp32 values -> two uint4 (16B) chunks
// ---------------------------------------------------------------------------
__device__ __forceinline__ void split8(const float* v, uint4& hi4, uint4& lo4) {
    uint32_t hi[4], lo[4];
    #pragma unroll
    for (int e = 0; e < 4; e++) {
        __nv_bfloat16 h0 = __float2bfloat16_rn(v[2 * e]);
        __nv_bfloat16 h1 = __float2bfloat16_rn(v[2 * e + 1]);
        __nv_bfloat16 l0 = __float2bfloat16_rn(v[2 * e] - __bfloat162float(h0));
        __nv_bfloat16 l1 = __float2bfloat16_rn(v[2 * e + 1] - __bfloat162float(h1));
        hi[e] = (uint32_t)__bfloat16_as_ushort(h0) | ((uint32_t)__bfloat16_as_ushort(h1) << 16);
        lo[e] = (uint32_t)__bfloat16_as_ushort(l0) | ((uint32_t)__bfloat16_as_ushort(l1) << 16);
    }
    hi4 = make_uint4(hi[0], hi[1], hi[2], hi[3]);
    lo4 = make_uint4(lo[0], lo[1], lo[2], lo[3]);
}

// ---------------------------------------------------------------------------
// Kernel 1: x (fp32 row-major) -> packed A_hi/A_lo tiles
// ---------------------------------------------------------------------------
__global__ void convert_x_kernel(const float* __restrict__ x) {
    int i = blockIdx.x * blockDim.x + threadIdx.x;    // one thread = 8 k-elems
    if (i >= MDIM * (KDIM / 8)) return;
    int m = i / (KDIM / 8);
    int k = (i % (KDIM / 8)) * 8;

    const float4* xp = reinterpret_cast<const float4*>(x + (size_t)m * KDIM + k);
    float4 v0 = xp[0], v1 = xp[1];
    float v[8] = {v0.x, v0.y, v0.z, v0.w, v1.x, v1.y, v1.z, v1.w};
    uint4 hi4, lo4;
    split8(v, hi4, lo4);

    int mt = m >> 7, r = m & 127, kt = k >> 5, c = (k & 31) >> 3;
    size_t off = ((size_t)mt * KT + kt) * TILE_G + r * 64 + c * 16;
    *reinterpret_cast<uint4*>(g_a_hi + off) = hi4;
    *reinterpret_cast<uint4*>(g_a_lo + off) = lo4;
}

// ---------------------------------------------------------------------------
// Kernel 2: dequant -> packed W_hi/W_lo tiles
// ---------------------------------------------------------------------------
__global__ void dequant_kernel(const int* __restrict__ indices,
                               const float* __restrict__ codebook,
                               const float* __restrict__ scales) {
    int i = blockIdx.x * blockDim.x + threadIdx.x;    // one thread = one 8-vector
    if (i >= NVEC) return;
    int n = i / (INF / 8);
    int k = (i % (INF / 8)) * 8;

    int code = indices[i];
    const float4* cb = reinterpret_cast<const float4*>(codebook) + (size_t)code * 2;
    float4 c0 = cb[0], c1 = cb[1];
    float s = __ldg(&scales[n]);
    float v[8] = {c0.x * s, c0.y * s, c0.z * s, c0.w * s,
                  c1.x * s, c1.y * s, c1.z * s, c1.w * s};
    uint4 hi4, lo4;
    split8(v, hi4, lo4);

    int nt = n >> 7, r = n & 127, kt = k >> 5, c = (k & 31) >> 3;
    size_t off = ((size_t)nt * KT + kt) * TILE_G + r * 64 + c * 16;
    *reinterpret_cast<uint4*>(g_w_hi + off) = hi4;
    *reinterpret_cast<uint4*>(g_w_lo + off) = lo4;
}

// ---------------------------------------------------------------------------
// Kernel 3: bf16 HMMA GEMM  C = A_hi·W_hiᵀ + A_hi·W_loᵀ + A_lo·W_hiᵀ
// 128x128 CTA, BK=32, 4-stage cp.async pipeline, warp tile 32x64 (m16n8k16)
// Mainloop: wait+sync -> ldsm ALL fragments -> issue next cp.async -> 96 MMA
// ---------------------------------------------------------------------------
__global__ void __launch_bounds__(256, 1)
gemm_kernel(float* __restrict__ C) {
    extern __shared__ __align__(1024) uint8_t smem[];
    const uint32_t sb = smem_u32(smem);
    const int tid = threadIdx.x;
    const int lane = tid & 31;
    const int wid = tid >> 5;
    const int wm = wid & 3;       // 4 m-warps  (32 rows each)
    const int wn = wid >> 2;      // 2 n-warps  (64 cols each)

    // grouped raster: 8 m-tiles per group for L2 reuse
    const int bid = blockIdx.x;
    const int mt = (bid >> 8) * 8 + (bid & 7);
    const int nt = (bid >> 3) & 31;

    const uint8_t* gbase[4] = {
        g_a_hi + (size_t)mt * KT * TILE_G,
        g_a_lo + (size_t)mt * KT * TILE_G,
        g_w_hi + (size_t)nt * KT * TILE_G,
        g_w_lo + (size_t)nt * KT * TILE_G,
    };

    // cp.async mapping: 2048 chunks/stage, 8 per thread
    auto load_stage = [&](int s, int kt) {
        #pragma unroll
        for (int j = 0; j < 8; j++) {
            int ch = tid + j * 256;
            int tile = ch >> 9;
            int row = (ch & 511) >> 2;
            int c = ch & 3;
            const uint8_t* gsrc = gbase[tile] + (size_t)kt * TILE_G + row * 64 + c * 16;
            uint32_t sdst = sb + s * STAGE_BYTES + tile * TILE_S + row * SROW + c * 16;
            cp_async16(sdst, gsrc);
        }
    };

    // prologue: fill NST-1 stages
    #pragma unroll
    for (int s = 0; s < NST - 1; s++) {
        load_stage(s, s);
        CP_COMMIT();
    }

    float acc[2][8][4];
    #pragma unroll
    for (int mi = 0; mi < 2; mi++)
        #pragma unroll
        for (int n8 = 0; n8 < 8; n8++)
            #pragma unroll
            for (int q = 0; q < 4; q++) acc[mi][n8][q] = 0.0f;

    // per-thread ldmatrix base offsets
    const uint32_t a_off = (uint32_t)(wm * 32 + (lane & 15)) * SROW + (lane >> 4) * 16;
    const uint32_t w_off = (uint32_t)(wn * 64 + (lane & 15)) * SROW + (lane >> 4) * 16;

    for (int k = 0; k < KT; k++) {
        const int s = k & (NST - 1);
        const uint32_t sAhi = sb + s * STAGE_BYTES;
        const uint32_t sAlo = sAhi + TILE_S;
        const uint32_t sWhi = sAhi + 2 * TILE_S;
        const uint32_t sWlo = sAhi + 3 * TILE_S;

        // stage s ready; sync also guarantees all warps finished iter k-1 ldsm
        CP_WAIT(NST - 2);
        __syncthreads();

        // ---- load ALL fragments for this k-step (one latency bubble) ----
        uint32_t ah[2][2][4], al[2][2][4], wh[4][2][4], wl[4][2][4];
        #pragma unroll
        for (int mi = 0; mi < 2; mi++)
            #pragma unroll
            for (int kh = 0; kh < 2; kh++) {
                ldsm4(ah[mi][kh], sAhi + a_off + mi * (16 * SROW) + kh * 32);
                ldsm4(al[mi][kh], sAlo + a_off + mi * (16 * SROW) + kh * 32);
            }
        #pragma unroll
        for (int ni = 0; ni < 4; ni++)
            #pragma unroll
            for (int kh = 0; kh < 2; kh++) {
                ldsm4(wh[ni][kh], sWhi + w_off + ni * (16 * SROW) + kh * 32);
                ldsm4(wl[ni][kh], sWlo + w_off + ni * (16 * SROW) + kh * 32);
            }

        // ---- issue next stage now; drains while MMAs run ----
        const int kn = k + NST - 1;
        if (kn < KT) load_stage(kn & (NST - 1), kn);
        CP_COMMIT();

        // ---- 96 MMAs, 16 independent accumulator chains ----
        #pragma unroll
        for (int kh = 0; kh < 2; kh++)
            #pragma unroll
            for (int mi = 0; mi < 2; mi++)
                #pragma unroll
                for (int n8 = 0; n8 < 8; n8++)
                    mma_bf16(acc[mi][n8], ah[mi][kh],
                             wh[n8 >> 1][kh][n8 & 1], wh[n8 >> 1][kh][2 + (n8 & 1)]);
        #pragma unroll
        for (int kh = 0; kh < 2; kh++)
            #pragma unroll
            for (int mi = 0; mi < 2; mi++)
                #pragma unroll
                for (int n8 = 0; n8 < 8; n8++)
                    mma_bf16(acc[mi][n8], al[mi][kh],
                             wh[n8 >> 1][kh][n8 & 1], wh[n8 >> 1][kh][2 + (n8 & 1)]);
        #pragma unroll
        for (int kh = 0; kh < 2; kh++)
            #pragma unroll
            for (int mi = 0; mi < 2; mi++)
                #pragma unroll
                for (int n8 = 0; n8 < 8; n8++)
                    mma_bf16(acc[mi][n8], ah[mi][kh],
                             wl[n8 >> 1][kh][n8 & 1], wl[n8 >> 1][kh][2 + (n8 & 1)]);
    }

    // epilogue: fragment -> gmem (fp32)
    const int row0 = mt * BM + wm * 32 + (lane >> 2);
    const int col0 = nt * BN + wn * 64 + (lane & 3) * 2;
    #pragma unroll
    for (int mi = 0; mi < 2; mi++) {
        #pragma unroll
        for (int n8 = 0; n8 < 8; n8++) {
            float* p0 = C + (size_t)(row0 + mi * 16) * NDIM + col0 + n8 * 8;
            float* p1 = C + (size_t)(row0 + mi * 16 + 8) * NDIM + col0 + n8 * 8;
            p0[0] = acc[mi][n8][0];
            p0[1] = acc[mi][n8][1];
            p1[0] = acc[mi][n8][2];
            p1[1] = acc[mi][n8][3];
        }
    }
}

// ---------------------------------------------------------------------------
// Launch: convert -> dequant -> gemm  (graph-capturable, no allocs/syncs)
// Inputs (metadata order): x fp32, indices int32, codebook fp32, scales fp32
// ---------------------------------------------------------------------------
extern "C" void kernel_launch(void* const* d_in, const int* in_sizes, int n_in,
                              void* d_out, int out_size) {
    const float* x        = (const float*)d_in[0];
    const int*   indices  = (const int*)d_in[1];
    const float* codebook = (const float*)d_in[2];
    const float* scales   = (const float*)d_in[3];
    float* out = (float*)d_out;

    convert_x_kernel<<<(MDIM * (KDIM / 8) + 255) / 256, 256>>>(x);
    dequant_kernel<<<(NVEC + 255) / 256, 256>>>(indices, codebook, scales);

    cudaFuncSetAttribute(gemm_kernel, cudaFuncAttributeMaxDynamicSharedMemorySize,
                         SMEM_TOTAL);
    gemm_kernel<<<MT * NT, 256, SMEM_TOTAL>>>(out);
}

// round 8
// speedup vs baseline: 1.0251x; 1.0251x over previous
#include <cuda_runtime.h>
#include <cuda_fp16.h>
#include <cuda_fp8.h>
#include <cstdint>

// ---------------------------------------------------------------------------
// Problem constants
// ---------------------------------------------------------------------------
#define OUTF 4096
#define INF  11008
#define MDIM 4096                 // 2*2048 tokens
#define NDIM OUTF
#define KDIM INF
#define NVEC (OUTF * (INF / 8))   // 5,636,096 code vectors

// GEMM tiling
#define BM 128
#define BN 128
#define BK 32
#define KT (KDIM / BK)            // 344
#define MT (MDIM / BM)            // 32
#define NT (NDIM / BN)            // 32

#define TILE_GH 8192              // fp16 gmem tile: 128 rows x 64B
#define TILE_G8 4096              // fp8  gmem tile: 128 rows x 32B
#define SROWH   80                // fp16 smem row stride (16B-mult, conflict-free)
#define SROW8   48                // fp8  smem row stride (16B-mult, conflict-free)
#define TILE_SH (128 * SROWH)     // 10240
#define TILE_S8 (128 * SROW8)     // 6144

// stage layout
#define OFF_AH  0
#define OFF_WH  (OFF_AH + TILE_SH)            // 10240
#define OFF_A8  (OFF_WH + TILE_SH)            // 20480
#define OFF_AL8 (OFF_A8 + TILE_S8)            // 26624
#define OFF_W8  (OFF_AL8 + TILE_S8)           // 32768
#define OFF_WL8 (OFF_W8 + TILE_S8)            // 38912
#define STAGE_BYTES 45056
#define NST 4
#define SMEM_TOTAL (NST * STAGE_BYTES)        // 180224

#define LO_SCALE 2048.0f          // 2^11
#define INV_LO_SCALE (1.0f / 2048.0f)

// Packed operand tiles (static device arrays: alloc-guard safe)
__device__ __align__(256) uint8_t g_a_hi[(size_t)MT * KT * TILE_GH];
__device__ __align__(256) uint8_t g_w_hi[(size_t)NT * KT * TILE_GH];
__device__ __align__(256) uint8_t g_a_f8[(size_t)MT * KT * TILE_G8];
__device__ __align__(256) uint8_t g_a_l8[(size_t)MT * KT * TILE_G8];
__device__ __align__(256) uint8_t g_w_f8[(size_t)NT * KT * TILE_G8];
__device__ __align__(256) uint8_t g_w_l8[(size_t)NT * KT * TILE_G8];

// ---------------------------------------------------------------------------
// PTX helpers (plain sm_80/sm_89 — compile at compute_103)
// ---------------------------------------------------------------------------
__device__ __forceinline__ uint32_t smem_u32(const void* p) {
    uint32_t a;
    asm("{ .reg .u64 t; cvta.to.shared.u64 t, %1; cvt.u32.u64 %0, t; }"
        : "=r"(a) : "l"(p));
    return a;
}

__device__ __forceinline__ void cp_async16(uint32_t sdst, const void* gsrc) {
    asm volatile("cp.async.cg.shared.global [%0], [%1], 16;"
                 :: "r"(sdst), "l"(gsrc) : "memory");
}
#define CP_COMMIT()  asm volatile("cp.async.commit_group;" ::: "memory")
#define CP_WAIT(n)   asm volatile("cp.async.wait_group %0;" :: "n"(n) : "memory")

__device__ __forceinline__ void ldsm4(uint32_t (&r)[4], uint32_t addr) {
    asm volatile("ldmatrix.sync.aligned.m8n8.x4.shared.b16 {%0,%1,%2,%3}, [%4];"
                 : "=r"(r[0]), "=r"(r[1]), "=r"(r[2]), "=r"(r[3]) : "r"(addr));
}

__device__ __forceinline__ void mma_f16(float (&c)[4], const uint32_t (&a)[4],
                                        uint32_t b0, uint32_t b1) {
    asm volatile(
        "mma.sync.aligned.m16n8k16.row.col.f32.f16.f16.f32 "
        "{%0,%1,%2,%3}, {%4,%5,%6,%7}, {%8,%9}, {%0,%1,%2,%3};"
        : "+f"(c[0]), "+f"(c[1]), "+f"(c[2]), "+f"(c[3])
        : "r"(a[0]), "r"(a[1]), "r"(a[2]), "r"(a[3]), "r"(b0), "r"(b1));
}

__device__ __forceinline__ void mma_f8(float (&c)[4], const uint32_t (&a)[4],
                                       uint32_t b0, uint32_t b1) {
    asm volatile(
        "mma.sync.aligned.m16n8k32.row.col.f32.e4m3.e4m3.f32 "
        "{%0,%1,%2,%3}, {%4,%5,%6,%7}, {%8,%9}, {%0,%1,%2,%3};"
        : "+f"(c[0]), "+f"(c[1]), "+f"(c[2]), "+f"(c[3])
        : "r"(a[0]), "r"(a[1]), "r"(a[2]), "r"(a[3]), "r"(b0), "r"(b1));
}

// ---------------------------------------------------------------------------
// Split 8 fp32 values -> fp16 hi (16B), fp8(v) (8B), fp8(residual*2^11) (8B)
// ---------------------------------------------------------------------------
__device__ __forceinline__ void split8(const float* v, uint4& hi4, uint2& f8,
                                       uint2& l8) {
    uint32_t h[4];
    uint16_t f[4], l[4];
    #pragma unroll
    for (int e = 0; e < 4; e++) {
        float v0 = v[2 * e], v1 = v[2 * e + 1];
        __half h0 = __float2half_rn(v0);
        __half h1 = __float2half_rn(v1);
        h[e] = (uint32_t)__half_as_ushort(h0) | ((uint32_t)__half_as_ushort(h1) << 16);
        float r0 = (v0 - __half2float(h0)) * LO_SCALE;
        float r1 = (v1 - __half2float(h1)) * LO_SCALE;
        f[e] = __nv_cvt_float2_to_fp8x2(make_float2(v0, v1), __NV_SATFINITE, __NV_E4M3);
        l[e] = __nv_cvt_float2_to_fp8x2(make_float2(r0, r1), __NV_SATFINITE, __NV_E4M3);
    }
    hi4 = make_uint4(h[0], h[1], h[2], h[3]);
    f8 = make_uint2((uint32_t)f[0] | ((uint32_t)f[1] << 16),
                    (uint32_t)f[2] | ((uint32_t)f[3] << 16));
    l8 = make_uint2((uint32_t)l[0] | ((uint32_t)l[1] << 16),
                    (uint32_t)l[2] | ((uint32_t)l[3] << 16));
}

// ---------------------------------------------------------------------------
// Kernel 1: x (fp32 row-major) -> Ah fp16 tiles + A8/Al8 fp8 tiles
// ---------------------------------------------------------------------------
__global__ void convert_x_kernel(const float* __restrict__ x) {
    int i = blockIdx.x * blockDim.x + threadIdx.x;    // one thread = 8 k-elems
    if (i >= MDIM * (KDIM / 8)) return;
    int m = i / (KDIM / 8);
    int k = (i % (KDIM / 8)) * 8;

    const float4* xp = reinterpret_cast<const float4*>(x + (size_t)m * KDIM + k);
    float4 v0 = xp[0], v1 = xp[1];
    float v[8] = {v0.x, v0.y, v0.z, v0.w, v1.x, v1.y, v1.z, v1.w};
    uint4 hi4; uint2 f8, l8;
    split8(v, hi4, f8, l8);

    int mt = m >> 7, r = m & 127, kt = k >> 5, c = (k & 31) >> 3;
    size_t tb = (size_t)mt * KT + kt;
    *reinterpret_cast<uint4*>(g_a_hi + tb * TILE_GH + r * 64 + c * 16) = hi4;
    *reinterpret_cast<uint2*>(g_a_f8 + tb * TILE_G8 + r * 32 + c * 8) = f8;
    *reinterpret_cast<uint2*>(g_a_l8 + tb * TILE_G8 + r * 32 + c * 8) = l8;
}

// ---------------------------------------------------------------------------
// Kernel 2: dequant -> Wh fp16 tiles + W8/Wl8 fp8 tiles
// ---------------------------------------------------------------------------
__global__ void dequant_kernel(const int* __restrict__ indices,
                               const float* __restrict__ codebook,
                               const float* __restrict__ scales) {
    int i = blockIdx.x * blockDim.x + threadIdx.x;    // one thread = one 8-vector
    if (i >= NVEC) return;
    int n = i / (INF / 8);
    int k = (i % (INF / 8)) * 8;

    int code = indices[i];
    const float4* cb = reinterpret_cast<const float4*>(codebook) + (size_t)code * 2;
    float4 c0 = cb[0], c1 = cb[1];
    float s = __ldg(&scales[n]);
    float v[8] = {c0.x * s, c0.y * s, c0.z * s, c0.w * s,
                  c1.x * s, c1.y * s, c1.z * s, c1.w * s};
    uint4 hi4; uint2 f8, l8;
    split8(v, hi4, f8, l8);

    int nt = n >> 7, r = n & 127, kt = k >> 5, c = (k & 31) >> 3;
    size_t tb = (size_t)nt * KT + kt;
    *reinterpret_cast<uint4*>(g_w_hi + tb * TILE_GH + r * 64 + c * 16) = hi4;
    *reinterpret_cast<uint2*>(g_w_f8 + tb * TILE_G8 + r * 32 + c * 8) = f8;
    *reinterpret_cast<uint2*>(g_w_l8 + tb * TILE_G8 + r * 32 + c * 8) = l8;
}

// ---------------------------------------------------------------------------
// Kernel 3: GEMM  C = Ah·Whᵀ (fp16) + 2^-11·(A8·Wl8ᵀ + Al8·W8ᵀ) (fp8 k32)
// 128x128 CTA, BK=32, 4-stage cp.async pipeline, warp tile 32x64
// R5-style phase-interleaved mainloop (ld -> mma per phase)
// ---------------------------------------------------------------------------
__global__ void __launch_bounds__(256, 1)
gemm_kernel(float* __restrict__ C) {
    extern __shared__ __align__(1024) uint8_t smem[];
    const uint32_t sb = smem_u32(smem);
    const int tid = threadIdx.x;
    const int lane = tid & 31;
    const int wid = tid >> 5;
    const int wm = wid & 3;       // 4 m-warps (32 rows each)
    const int wn = wid >> 2;      // 2 n-warps (64 cols each)

    // grouped raster: 8 m-tiles per group for L2 reuse
    const int bid = blockIdx.x;
    const int mt = (bid >> 8) * 8 + (bid & 7);
    const int nt = (bid >> 3) & 31;

    const uint8_t* gAh  = g_a_hi + (size_t)mt * KT * TILE_GH;
    const uint8_t* gWh  = g_w_hi + (size_t)nt * KT * TILE_GH;
    const uint8_t* gA8  = g_a_f8 + (size_t)mt * KT * TILE_G8;
    const uint8_t* gAl8 = g_a_l8 + (size_t)mt * KT * TILE_G8;
    const uint8_t* gW8  = g_w_f8 + (size_t)nt * KT * TILE_G8;
    const uint8_t* gWl8 = g_w_l8 + (size_t)nt * KT * TILE_G8;

    // cp.async: 2048 chunks/stage, 8 per thread
    auto load_stage = [&](int s, int kt) {
        const uint32_t st = sb + s * STAGE_BYTES;
        {   // Ah (512 chunks)
            #pragma unroll
            for (int j = 0; j < 2; j++) {
                int idx = tid + j * 256;
                int row = idx >> 2, c = idx & 3;
                cp_async16(st + OFF_AH + row * SROWH + c * 16,
                           gAh + (size_t)kt * TILE_GH + row * 64 + c * 16);
            }
        }
        {   // Wh (512 chunks)
            #pragma unroll
            for (int j = 0; j < 2; j++) {
                int idx = tid + j * 256;
                int row = idx >> 2, c = idx & 3;
                cp_async16(st + OFF_WH + row * SROWH + c * 16,
                           gWh + (size_t)kt * TILE_GH + row * 64 + c * 16);
            }
        }
        {   // fp8 tiles (256 chunks each)
            int row = tid >> 1, c = tid & 1;
            uint32_t d = row * SROW8 + c * 16;
            size_t g = (size_t)kt * TILE_G8 + row * 32 + c * 16;
            cp_async16(st + OFF_A8 + d, gA8 + g);
            cp_async16(st + OFF_AL8 + d, gAl8 + g);
            cp_async16(st + OFF_W8 + d, gW8 + g);
            cp_async16(st + OFF_WL8 + d, gWl8 + g);
        }
    };

    // prologue: fill NST-1 stages
    #pragma unroll
    for (int s = 0; s < NST - 1; s++) {
        load_stage(s, s);
        CP_COMMIT();
    }
    CP_WAIT(NST - 2);
    __syncthreads();

    float acc[2][8][4];   // fp16 hi accumulator
    float acc8[2][8][4];  // fp8 cross-term accumulator (scaled by 2^-11 at end)
    #pragma unroll
    for (int mi = 0; mi < 2; mi++)
        #pragma unroll
        for (int n8 = 0; n8 < 8; n8++)
            #pragma unroll
            for (int q = 0; q < 4; q++) { acc[mi][n8][q] = 0.0f; acc8[mi][n8][q] = 0.0f; }

    // per-thread ldmatrix base offsets
    const uint32_t aH_off = (uint32_t)(wm * 32 + (lane & 15)) * SROWH + (lane >> 4) * 16;
    const uint32_t wH_off = (uint32_t)(wn * 64 + (lane & 15)) * SROWH + (lane >> 4) * 16;
    const uint32_t a8_off = (uint32_t)(wm * 32 + (lane & 15)) * SROW8 + (lane >> 4) * 16;
    const uint32_t w8_off = (uint32_t)(wn * 64 + (lane & 15)) * SROW8 + (lane >> 4) * 16;

    for (int k = 0; k < KT; k++) {
        const int s = k & (NST - 1);
        const uint32_t st = sb + s * STAGE_BYTES;

        // ---- phase 1: fp16 hh ----
        uint32_t ah[2][2][4], wh[4][2][4];
        #pragma unroll
        for (int mi = 0; mi < 2; mi++)
            #pragma unroll
            for (int kh = 0; kh < 2; kh++)
                ldsm4(ah[mi][kh], st + OFF_AH + aH_off + mi * (16 * SROWH) + kh * 32);
        #pragma unroll
        for (int ni = 0; ni < 4; ni++)
            #pragma unroll
            for (int kh = 0; kh < 2; kh++)
                ldsm4(wh[ni][kh], st + OFF_WH + wH_off + ni * (16 * SROWH) + kh * 32);
        #pragma unroll
        for (int kh = 0; kh < 2; kh++)
            #pragma unroll
            for (int mi = 0; mi < 2; mi++)
                #pragma unroll
                for (int n8 = 0; n8 < 8; n8++)
                    mma_f16(acc[mi][n8], ah[mi][kh],
                            wh[n8 >> 1][kh][n8 & 1], wh[n8 >> 1][kh][2 + (n8 & 1)]);

        // ---- phase 2: A8 x Wl8 (fp8, k32 per instr) ----
        uint32_t a8[2][4], wl8[4][4];
        #pragma unroll
        for (int mi = 0; mi < 2; mi++)
            ldsm4(a8[mi], st + OFF_A8 + a8_off + mi * (16 * SROW8));
        #pragma unroll
        for (int ni = 0; ni < 4; ni++)
            ldsm4(wl8[ni], st + OFF_WL8 + w8_off + ni * (16 * SROW8));
        #pragma unroll
        for (int mi = 0; mi < 2; mi++)
            #pragma unroll
            for (int n8 = 0; n8 < 8; n8++)
                mma_f8(acc8[mi][n8], a8[mi],
                       wl8[n8 >> 1][n8 & 1], wl8[n8 >> 1][2 + (n8 & 1)]);

        // ---- phase 3: Al8 x W8 (fp8, k32 per instr) ----
        uint32_t al8[2][4], w8[4][4];
        #pragma unroll
        for (int mi = 0; mi < 2; mi++)
            ldsm4(al8[mi], st + OFF_AL8 + a8_off + mi * (16 * SROW8));
        #pragma unroll
        for (int ni = 0; ni < 4; ni++)
            ldsm4(w8[ni], st + OFF_W8 + w8_off + ni * (16 * SROW8));
        #pragma unroll
        for (int mi = 0; mi < 2; mi++)
            #pragma unroll
            for (int n8 = 0; n8 < 8; n8++)
                mma_f8(acc8[mi][n8], al8[mi],
                       w8[n8 >> 1][n8 & 1], w8[n8 >> 1][2 + (n8 & 1)]);

        // ---- issue next stage, advance pipeline ----
        const int kn = k + NST - 1;
        if (kn < KT) load_stage(kn & (NST - 1), kn);
        CP_COMMIT();
        CP_WAIT(NST - 2);
        __syncthreads();
    }

    // epilogue: combine accumulators, store fp32
    const int row0 = mt * BM + wm * 32 + (lane >> 2);
    const int col0 = nt * BN + wn * 64 + (lane & 3) * 2;
    #pragma unroll
    for (int mi = 0; mi < 2; mi++) {
        #pragma unroll
        for (int n8 = 0; n8 < 8; n8++) {
            float o0 = acc[mi][n8][0] + acc8[mi][n8][0] * INV_LO_SCALE;
            float o1 = acc[mi][n8][1] + acc8[mi][n8][1] * INV_LO_SCALE;
            float o2 = acc[mi][n8][2] + acc8[mi][n8][2] * INV_LO_SCALE;
            float o3 = acc[mi][n8][3] + acc8[mi][n8][3] * INV_LO_SCALE;
            float* p0 = C + (size_t)(row0 + mi * 16) * NDIM + col0 + n8 * 8;
            float* p1 = C + (size_t)(row0 + mi * 16 + 8) * NDIM + col0 + n8 * 8;
            p0[0] = o0; p0[1] = o1;
            p1[0] = o2; p1[1] = o3;
        }
    }
}

// ---------------------------------------------------------------------------
// Launch: convert -> dequant -> gemm  (graph-capturable, no allocs/syncs)
// Inputs (metadata order): x fp32, indices int32, codebook fp32, scales fp32
// ---------------------------------------------------------------------------
extern "C" void kernel_launch(void* const* d_in, const int* in_sizes, int n_in,
                              void* d_out, int out_size) {
    const float* x        = (const float*)d_in[0];
    const int*   indices  = (const int*)d_in[1];
    const float* codebook = (const float*)d_in[2];
    const float* scales   = (const float*)d_in[3];
    float* out = (float*)d_out;

    convert_x_kernel<<<(MDIM * (KDIM / 8) + 255) / 256, 256>>>(x);
    dequant_kernel<<<(NVEC + 255) / 256, 256>>>(indices, codebook, scales);

    cudaFuncSetAttribute(gemm_kernel, cudaFuncAttributeMaxDynamicSharedMemorySize,
                         SMEM_TOTAL);
    gemm_kernel<<<MT * NT, 256, SMEM_TOTAL>>>(out);
}

// round 9
// speedup vs baseline: 1.4665x; 1.4306x over previous
#include <cuda_runtime.h>
#include <cuda_bf16.h>
#include <cstdint>

// ---------------------------------------------------------------------------
// Problem constants
// ---------------------------------------------------------------------------
#define OUTF 4096
#define INF  11008
#define MDIM 4096                 // 2*2048 tokens
#define NDIM OUTF
#define KDIM INF
#define NVEC (OUTF * (INF / 8))   // 5,636,096 code vectors

// GEMM tiling
#define BM 128
#define BN 128
#define BK 32
#define KT (KDIM / BK)            // 344
#define MT (MDIM / BM)            // 32
#define NT (NDIM / BN)            // 32

#define TILE_G 8192               // packed gmem tile: 128 rows x 64B (linear)
#define TILE_S 8192               // smem tile: 128 rows x 64B (XOR-swizzled)
#define NST 3
#define STAGE_BYTES (4 * TILE_S)  // 32768 (Ahi, Alo, Whi, Wlo)
#define SMEM_TOTAL (NST * STAGE_BYTES)   // 98304 -> 2 CTAs/SM

// Packed bf16 operand tiles (static device arrays: alloc-guard safe)
__device__ __align__(256) uint8_t g_a_hi[(size_t)MT * KT * TILE_G];
__device__ __align__(256) uint8_t g_a_lo[(size_t)MT * KT * TILE_G];
__device__ __align__(256) uint8_t g_w_hi[(size_t)NT * KT * TILE_G];
__device__ __align__(256) uint8_t g_w_lo[(size_t)NT * KT * TILE_G];

// ---------------------------------------------------------------------------
// PTX helpers (plain sm_80+ — compile at compute_103)
// ---------------------------------------------------------------------------
__device__ __forceinline__ uint32_t smem_u32(const void* p) {
    uint32_t a;
    asm("{ .reg .u64 t; cvta.to.shared.u64 t, %1; cvt.u32.u64 %0, t; }"
        : "=r"(a) : "l"(p));
    return a;
}

__device__ __forceinline__ void cp_async16(uint32_t sdst, const void* gsrc) {
    asm volatile("cp.async.cg.shared.global [%0], [%1], 16;"
                 :: "r"(sdst), "l"(gsrc) : "memory");
}
#define CP_COMMIT()  asm volatile("cp.async.commit_group;" ::: "memory")
#define CP_WAIT(n)   asm volatile("cp.async.wait_group %0;" :: "n"(n) : "memory")

__device__ __forceinline__ void ldsm4(uint32_t (&r)[4], uint32_t addr) {
    asm volatile("ldmatrix.sync.aligned.m8n8.x4.shared.b16 {%0,%1,%2,%3}, [%4];"
                 : "=r"(r[0]), "=r"(r[1]), "=r"(r[2]), "=r"(r[3]) : "r"(addr));
}

__device__ __forceinline__ void mma_bf16(float (&c)[4], const uint32_t (&a)[4],
                                         uint32_t b0, uint32_t b1) {
    asm volatile(
        "mma.sync.aligned.m16n8k16.row.col.f32.bf16.bf16.f32 "
        "{%0,%1,%2,%3}, {%4,%5,%6,%7}, {%8,%9}, {%0,%1,%2,%3};"
        : "+f"(c[0]), "+f"(c[1]), "+f"(c[2]), "+f"(c[3])
        : "r"(a[0]), "r"(a[1]), "r"(a[2]), "r"(a[3]), "r"(b0), "r"(b1));
}

// ---------------------------------------------------------------------------
// hi/lo bf16 split of 8 fp32 values -> two uint4 (16B) chunks
// ---------------------------------------------------------------------------
__device__ __forceinline__ void split8(const float* v, uint4& hi4, uint4& lo4) {
    uint32_t hi[4], lo[4];
    #pragma unroll
    for (int e = 0; e < 4; e++) {
        __nv_bfloat16 h0 = __float2bfloat16_rn(v[2 * e]);
        __nv_bfloat16 h1 = __float2bfloat16_rn(v[2 * e + 1]);
        __nv_bfloat16 l0 = __float2bfloat16_rn(v[2 * e] - __bfloat162float(h0));
        __nv_bfloat16 l1 = __float2bfloat16_rn(v[2 * e + 1] - __bfloat162float(h1));
        hi[e] = (uint32_t)__bfloat16_as_ushort(h0) | ((uint32_t)__bfloat16_as_ushort(h1) << 16);
        lo[e] = (uint32_t)__bfloat16_as_ushort(l0) | ((uint32_t)__bfloat16_as_ushort(l1) << 16);
    }
    hi4 = make_uint4(hi[0], hi[1], hi[2], hi[3]);
    lo4 = make_uint4(lo[0], lo[1], lo[2], lo[3]);
}

// ---------------------------------------------------------------------------
// Kernel 1: x (fp32 row-major) -> packed A_hi/A_lo tiles (linear 128x64B)
// ---------------------------------------------------------------------------
__global__ void convert_x_kernel(const float* __restrict__ x) {
    int i = blockIdx.x * blockDim.x + threadIdx.x;    // one thread = 8 k-elems
    if (i >= MDIM * (KDIM / 8)) return;
    int m = i / (KDIM / 8);
    int k = (i % (KDIM / 8)) * 8;

    const float4* xp = reinterpret_cast<const float4*>(x + (size_t)m * KDIM + k);
    float4 v0 = xp[0], v1 = xp[1];
    float v[8] = {v0.x, v0.y, v0.z, v0.w, v1.x, v1.y, v1.z, v1.w};
    uint4 hi4, lo4;
    split8(v, hi4, lo4);

    int mt = m >> 7, r = m & 127, kt = k >> 5, c = (k & 31) >> 3;
    size_t off = ((size_t)mt * KT + kt) * TILE_G + r * 64 + c * 16;
    *reinterpret_cast<uint4*>(g_a_hi + off) = hi4;
    *reinterpret_cast<uint4*>(g_a_lo + off) = lo4;
}

// ---------------------------------------------------------------------------
// Kernel 2: dequant -> packed W_hi/W_lo tiles (linear 128x64B)
// ---------------------------------------------------------------------------
__global__ void dequant_kernel(const int* __restrict__ indices,
                               const float* __restrict__ codebook,
                               const float* __restrict__ scales) {
    int i = blockIdx.x * blockDim.x + threadIdx.x;    // one thread = one 8-vector
    if (i >= NVEC) return;
    int n = i / (INF / 8);
    int k = (i % (INF / 8)) * 8;

    int code = indices[i];
    const float4* cb = reinterpret_cast<const float4*>(codebook) + (size_t)code * 2;
    float4 c0 = cb[0], c1 = cb[1];
    float s = __ldg(&scales[n]);
    float v[8] = {c0.x * s, c0.y * s, c0.z * s, c0.w * s,
                  c1.x * s, c1.y * s, c1.z * s, c1.w * s};
    uint4 hi4, lo4;
    split8(v, hi4, lo4);

    int nt = n >> 7, r = n & 127, kt = k >> 5, c = (k & 31) >> 3;
    size_t off = ((size_t)nt * KT + kt) * TILE_G + r * 64 + c * 16;
    *reinterpret_cast<uint4*>(g_w_hi + off) = hi4;
    *reinterpret_cast<uint4*>(g_w_lo + off) = lo4;
}

// ---------------------------------------------------------------------------
// Kernel 3: bf16 HMMA GEMM  C = A_hi·W_hiᵀ + A_lo·W_hiᵀ + A_hi·W_loᵀ
// 128x128 CTA, BK=32, NST=3 cp.async pipeline, XOR-swizzled smem,
// 2 CTAs/SM, R5 phase-interleaved mainloop, 1 syncthreads/iter
// smem swizzle: byte = row*64 + (c ^ ((row>>1)&3))*16
// ---------------------------------------------------------------------------
__global__ void __launch_bounds__(256, 2)
gemm_kernel(float* __restrict__ C) {
    extern __shared__ __align__(1024) uint8_t smem[];
    const uint32_t sb = smem_u32(smem);
    const int tid = threadIdx.x;
    const int lane = tid & 31;
    const int wid = tid >> 5;
    const int wm = wid & 3;       // 4 m-warps (32 rows each)
    const int wn = wid >> 2;      // 2 n-warps (64 cols each)

    // grouped raster: 8 m-tiles per group for L2 reuse
    const int bid = blockIdx.x;
    const int mt = (bid >> 8) * 8 + (bid & 7);
    const int nt = (bid >> 3) & 31;

    const uint8_t* gbase[4] = {
        g_a_hi + (size_t)mt * KT * TILE_G,
        g_a_lo + (size_t)mt * KT * TILE_G,
        g_w_hi + (size_t)nt * KT * TILE_G,
        g_w_lo + (size_t)nt * KT * TILE_G,
    };

    // cp.async mapping: 2048 chunks/stage, 8 per thread
    // ch = tid + j*256 : tile=ch>>9, row=(ch&511)>>2, c=ch&3 (swizzled dst)
    auto load_stage = [&](int s, int kt) {
        #pragma unroll
        for (int j = 0; j < 8; j++) {
            int ch = tid + j * 256;
            int tile = ch >> 9;
            int row = (ch & 511) >> 2;
            int c = ch & 3;
            int cs = c ^ ((row >> 1) & 3);
            const uint8_t* gsrc = gbase[tile] + (size_t)kt * TILE_G + row * 64 + c * 16;
            uint32_t sdst = sb + s * STAGE_BYTES + tile * TILE_S + row * 64 + cs * 16;
            cp_async16(sdst, gsrc);
        }
    };

    // prologue: fill NST-1 stages
    #pragma unroll
    for (int s = 0; s < NST - 1; s++) {
        load_stage(s, s);
        CP_COMMIT();
    }
    CP_WAIT(NST - 2);
    __syncthreads();

    float acc[2][8][4];
    #pragma unroll
    for (int mi = 0; mi < 2; mi++)
        #pragma unroll
        for (int n8 = 0; n8 < 8; n8++)
            #pragma unroll
            for (int q = 0; q < 4; q++) acc[mi][n8][q] = 0.0f;

    // per-thread ldmatrix addressing (swizzle select constant per thread:
    // row = base + (lane&15) + {0,16,...}; adding multiples of 16 doesn't
    // change (row>>1)&3, nor do wm*32 / wn*64)
    const int hb = lane >> 4;                 // 16B half select
    const int rA = (lane & 15);
    const int selA = (rA >> 1) & 3;
    const uint32_t a_row_off = (uint32_t)(wm * 32 + rA) * 64;
    const uint32_t w_row_off = (uint32_t)(wn * 64 + rA) * 64;
    // physical chunk offsets for kh=0,1
    const uint32_t ck0 = (uint32_t)(((0 * 2 + hb) ^ selA) * 16);
    const uint32_t ck1 = (uint32_t)(((1 * 2 + hb) ^ selA) * 16);

    int stage = 0;
    for (int k = 0; k < KT; k++) {
        const uint32_t st = sb + stage * STAGE_BYTES;
        const uint32_t sAhi = st;
        const uint32_t sAlo = st + TILE_S;
        const uint32_t sWhi = st + 2 * TILE_S;
        const uint32_t sWlo = st + 3 * TILE_S;

        // ---- phase 1: hi x hi ----
        uint32_t ah[2][2][4], wh[4][2][4];
        #pragma unroll
        for (int mi = 0; mi < 2; mi++) {
            ldsm4(ah[mi][0], sAhi + a_row_off + mi * 1024 + ck0);
            ldsm4(ah[mi][1], sAhi + a_row_off + mi * 1024 + ck1);
        }
        #pragma unroll
        for (int ni = 0; ni < 4; ni++) {
            ldsm4(wh[ni][0], sWhi + w_row_off + ni * 1024 + ck0);
            ldsm4(wh[ni][1], sWhi + w_row_off + ni * 1024 + ck1);
        }
        #pragma unroll
        for (int kh = 0; kh < 2; kh++)
            #pragma unroll
            for (int mi = 0; mi < 2; mi++)
                #pragma unroll
                for (int n8 = 0; n8 < 8; n8++)
                    mma_bf16(acc[mi][n8], ah[mi][kh],
                             wh[n8 >> 1][kh][n8 & 1], wh[n8 >> 1][kh][2 + (n8 & 1)]);

        // ---- phase 2: lo x hi ----
        uint32_t al[2][2][4];
        #pragma unroll
        for (int mi = 0; mi < 2; mi++) {
            ldsm4(al[mi][0], sAlo + a_row_off + mi * 1024 + ck0);
            ldsm4(al[mi][1], sAlo + a_row_off + mi * 1024 + ck1);
        }
        #pragma unroll
        for (int kh = 0; kh < 2; kh++)
            #pragma unroll
            for (int mi = 0; mi < 2; mi++)
                #pragma unroll
                for (int n8 = 0; n8 < 8; n8++)
                    mma_bf16(acc[mi][n8], al[mi][kh],
                             wh[n8 >> 1][kh][n8 & 1], wh[n8 >> 1][kh][2 + (n8 & 1)]);

        // ---- phase 3: hi x lo ----
        uint32_t wl[4][2][4];
        #pragma unroll
        for (int ni = 0; ni < 4; ni++) {
            ldsm4(wl[ni][0], sWlo + w_row_off + ni * 1024 + ck0);
            ldsm4(wl[ni][1], sWlo + w_row_off + ni * 1024 + ck1);
        }
        #pragma unroll
        for (int kh = 0; kh < 2; kh++)
            #pragma unroll
            for (int mi = 0; mi < 2; mi++)
                #pragma unroll
                for (int n8 = 0; n8 < 8; n8++)
                    mma_bf16(acc[mi][n8], ah[mi][kh],
                             wl[n8 >> 1][kh][n8 & 1], wl[n8 >> 1][kh][2 + (n8 & 1)]);

        // ---- issue next stage, advance pipeline (1 sync/iter, NST=3) ----
        const int kn = k + NST - 1;
        if (kn < KT) {
            int sn = stage + NST - 1;
            if (sn >= NST) sn -= NST;
            load_stage(sn, kn);
        }
        CP_COMMIT();
        CP_WAIT(NST - 2);
        __syncthreads();
        if (++stage == NST) stage = 0;
    }

    // epilogue: fragment -> gmem (fp32)
    const int row0 = mt * BM + wm * 32 + (lane >> 2);
    const int col0 = nt * BN + wn * 64 + (lane & 3) * 2;
    #pragma unroll
    for (int mi = 0; mi < 2; mi++) {
        #pragma unroll
        for (int n8 = 0; n8 < 8; n8++) {
            float* p0 = C + (size_t)(row0 + mi * 16) * NDIM + col0 + n8 * 8;
            float* p1 = C + (size_t)(row0 + mi * 16 + 8) * NDIM + col0 + n8 * 8;
            p0[0] = acc[mi][n8][0];
            p0[1] = acc[mi][n8][1];
            p1[0] = acc[mi][n8][2];
            p1[1] = acc[mi][n8][3];
        }
    }
}

// ---------------------------------------------------------------------------
// Launch: convert -> dequant -> gemm  (graph-capturable, no allocs/syncs)
// Inputs (metadata order): x fp32, indices int32, codebook fp32, scales fp32
// ---------------------------------------------------------------------------
extern "C" void kernel_launch(void* const* d_in, const int* in_sizes, int n_in,
                              void* d_out, int out_size) {
    const float* x        = (const float*)d_in[0];
    const int*   indices  = (const int*)d_in[1];
    const float* codebook = (const float*)d_in[2];
    const float* scales   = (const float*)d_in[3];
    float* out = (float*)d_out;

    convert_x_kernel<<<(MDIM * (KDIM / 8) + 255) / 256, 256>>>(x);
    dequant_kernel<<<(NVEC + 255) / 256, 256>>>(indices, codebook, scales);

    cudaFuncSetAttribute(gemm_kernel, cudaFuncAttributeMaxDynamicSharedMemorySize,
                         SMEM_TOTAL);
    gemm_kernel<<<MT * NT, 256, SMEM_TOTAL>>>(out);
}

// round 10
// speedup vs baseline: 2.2574x; 1.5394x over previous
#include <cuda_runtime.h>
#include <cuda_fp16.h>
#include <cstdint>

// ---------------------------------------------------------------------------
// Problem constants
// ---------------------------------------------------------------------------
#define OUTF 4096
#define INF  11008
#define MDIM 4096                 // 2*2048 tokens
#define NDIM OUTF
#define KDIM INF
#define NVEC (OUTF * (INF / 8))   // 5,636,096 code vectors

// GEMM tiling
#define BM 128
#define BN 128
#define BK 32
#define KT (KDIM / BK)            // 344
#define MT (MDIM / BM)            // 32
#define NT (NDIM / BN)            // 32

#define TILE_G 8192               // packed gmem tile: 128 rows x 64B (linear)
#define TILE_S 8192               // smem tile: 128 rows x 64B (XOR-swizzled)
#define NST 4
#define STAGE_BYTES (3 * TILE_S)  // 24576 (A16, W16h, W16l)
#define SMEM_TOTAL (NST * STAGE_BYTES)   // 98304 -> 2 CTAs/SM

// Packed fp16 operand tiles (static device arrays: alloc-guard safe)
__device__ __align__(256) uint8_t g_a16 [(size_t)MT * KT * TILE_G];
__device__ __align__(256) uint8_t g_w_hi[(size_t)NT * KT * TILE_G];
__device__ __align__(256) uint8_t g_w_lo[(size_t)NT * KT * TILE_G];

// ---------------------------------------------------------------------------
// PTX helpers (plain sm_80+ — compile at compute_103)
// ---------------------------------------------------------------------------
__device__ __forceinline__ uint32_t smem_u32(const void* p) {
    uint32_t a;
    asm("{ .reg .u64 t; cvta.to.shared.u64 t, %1; cvt.u32.u64 %0, t; }"
        : "=r"(a) : "l"(p));
    return a;
}

__device__ __forceinline__ void cp_async16(uint32_t sdst, const void* gsrc) {
    asm volatile("cp.async.cg.shared.global [%0], [%1], 16;"
                 :: "r"(sdst), "l"(gsrc) : "memory");
}
#define CP_COMMIT()  asm volatile("cp.async.commit_group;" ::: "memory")
#define CP_WAIT(n)   asm volatile("cp.async.wait_group %0;" :: "n"(n) : "memory")

__device__ __forceinline__ void ldsm4(uint32_t (&r)[4], uint32_t addr) {
    asm volatile("ldmatrix.sync.aligned.m8n8.x4.shared.b16 {%0,%1,%2,%3}, [%4];"
                 : "=r"(r[0]), "=r"(r[1]), "=r"(r[2]), "=r"(r[3]) : "r"(addr));
}

__device__ __forceinline__ void mma_f16(float (&c)[4], const uint32_t (&a)[4],
                                        uint32_t b0, uint32_t b1) {
    asm volatile(
        "mma.sync.aligned.m16n8k16.row.col.f32.f16.f16.f32 "
        "{%0,%1,%2,%3}, {%4,%5,%6,%7}, {%8,%9}, {%0,%1,%2,%3};"
        : "+f"(c[0]), "+f"(c[1]), "+f"(c[2]), "+f"(c[3])
        : "r"(a[0]), "r"(a[1]), "r"(a[2]), "r"(a[3]), "r"(b0), "r"(b1));
}

// ---------------------------------------------------------------------------
// Kernel 1: x (fp32 row-major) -> packed A16 fp16 tiles (linear 128x64B)
// ---------------------------------------------------------------------------
__global__ void convert_x_kernel(const float* __restrict__ x) {
    int i = blockIdx.x * blockDim.x + threadIdx.x;    // one thread = 8 k-elems
    if (i >= MDIM * (KDIM / 8)) return;
    int m = i / (KDIM / 8);
    int k = (i % (KDIM / 8)) * 8;

    const float4* xp = reinterpret_cast<const float4*>(x + (size_t)m * KDIM + k);
    float4 v0 = xp[0], v1 = xp[1];
    float v[8] = {v0.x, v0.y, v0.z, v0.w, v1.x, v1.y, v1.z, v1.w};

    uint32_t h[4];
    #pragma unroll
    for (int e = 0; e < 4; e++) {
        __half h0 = __float2half_rn(v[2 * e]);
        __half h1 = __float2half_rn(v[2 * e + 1]);
        h[e] = (uint32_t)__half_as_ushort(h0) | ((uint32_t)__half_as_ushort(h1) << 16);
    }

    int mt = m >> 7, r = m & 127, kt = k >> 5, c = (k & 31) >> 3;
    size_t off = ((size_t)mt * KT + kt) * TILE_G + r * 64 + c * 16;
    *reinterpret_cast<uint4*>(g_a16 + off) = make_uint4(h[0], h[1], h[2], h[3]);
}

// ---------------------------------------------------------------------------
// Kernel 2: dequant -> packed W16h/W16l fp16 tiles (linear 128x64B)
// ---------------------------------------------------------------------------
__global__ void dequant_kernel(const int* __restrict__ indices,
                               const float* __restrict__ codebook,
                               const float* __restrict__ scales) {
    int i = blockIdx.x * blockDim.x + threadIdx.x;    // one thread = one 8-vector
    if (i >= NVEC) return;
    int n = i / (INF / 8);
    int k = (i % (INF / 8)) * 8;

    int code = indices[i];
    const float4* cb = reinterpret_cast<const float4*>(codebook) + (size_t)code * 2;
    float4 c0 = cb[0], c1 = cb[1];
    float s = __ldg(&scales[n]);
    float v[8] = {c0.x * s, c0.y * s, c0.z * s, c0.w * s,
                  c1.x * s, c1.y * s, c1.z * s, c1.w * s};

    uint32_t hi[4], lo[4];
    #pragma unroll
    for (int e = 0; e < 4; e++) {
        __half h0 = __float2half_rn(v[2 * e]);
        __half h1 = __float2half_rn(v[2 * e + 1]);
        __half l0 = __float2half_rn(v[2 * e] - __half2float(h0));
        __half l1 = __float2half_rn(v[2 * e + 1] - __half2float(h1));
        hi[e] = (uint32_t)__half_as_ushort(h0) | ((uint32_t)__half_as_ushort(h1) << 16);
        lo[e] = (uint32_t)__half_as_ushort(l0) | ((uint32_t)__half_as_ushort(l1) << 16);
    }

    int nt = n >> 7, r = n & 127, kt = k >> 5, c = (k & 31) >> 3;
    size_t off = ((size_t)nt * KT + kt) * TILE_G + r * 64 + c * 16;
    *reinterpret_cast<uint4*>(g_w_hi + off) = make_uint4(hi[0], hi[1], hi[2], hi[3]);
    *reinterpret_cast<uint4*>(g_w_lo + off) = make_uint4(lo[0], lo[1], lo[2], lo[3]);
}

// ---------------------------------------------------------------------------
// Kernel 3: fp16 HMMA GEMM  C = A16·W16hᵀ + A16·W16lᵀ
// 128x128 CTA, BK=32, NST=4 cp.async pipeline, XOR-swizzled smem,
// 2 CTAs/SM, phase-interleaved mainloop (A fragments reused), 1 sync/iter
// smem swizzle: byte = row*64 + (c ^ ((row>>1)&3))*16
// ---------------------------------------------------------------------------
__global__ void __launch_bounds__(256, 2)
gemm_kernel(float* __restrict__ C) {
    extern __shared__ __align__(1024) uint8_t smem[];
    const uint32_t sb = smem_u32(smem);
    const int tid = threadIdx.x;
    const int lane = tid & 31;
    const int wid = tid >> 5;
    const int wm = wid & 3;       // 4 m-warps (32 rows each)
    const int wn = wid >> 2;      // 2 n-warps (64 cols each)

    // grouped raster: 8 m-tiles per group for L2 reuse
    const int bid = blockIdx.x;
    const int mt = (bid >> 8) * 8 + (bid & 7);
    const int nt = (bid >> 3) & 31;

    const uint8_t* gbase[3] = {
        g_a16  + (size_t)mt * KT * TILE_G,
        g_w_hi + (size_t)nt * KT * TILE_G,
        g_w_lo + (size_t)nt * KT * TILE_G,
    };

    // cp.async mapping: 1536 chunks/stage, 6 per thread
    // ch = tid + j*256 : tile=ch/512, row=(ch%512)>>2, c=ch&3 (swizzled dst)
    auto load_stage = [&](int s, int kt) {
        #pragma unroll
        for (int j = 0; j < 6; j++) {
            int ch = tid + j * 256;
            int tile = ch >> 9;
            int row = (ch & 511) >> 2;
            int c = ch & 3;
            int cs = c ^ ((row >> 1) & 3);
            const uint8_t* gsrc = gbase[tile] + (size_t)kt * TILE_G + row * 64 + c * 16;
            uint32_t sdst = sb + s * STAGE_BYTES + tile * TILE_S + row * 64 + cs * 16;
            cp_async16(sdst, gsrc);
        }
    };

    // prologue: fill NST-1 stages
    #pragma unroll
    for (int s = 0; s < NST - 1; s++) {
        load_stage(s, s);
        CP_COMMIT();
    }
    CP_WAIT(NST - 2);
    __syncthreads();

    float acc[2][8][4];
    #pragma unroll
    for (int mi = 0; mi < 2; mi++)
        #pragma unroll
        for (int n8 = 0; n8 < 8; n8++)
            #pragma unroll
            for (int q = 0; q < 4; q++) acc[mi][n8][q] = 0.0f;

    // per-thread ldmatrix addressing (swizzle select constant per thread)
    const int hb = lane >> 4;                 // 16B half select
    const int rA = (lane & 15);
    const int selA = (rA >> 1) & 3;
    const uint32_t a_row_off = (uint32_t)(wm * 32 + rA) * 64;
    const uint32_t w_row_off = (uint32_t)(wn * 64 + rA) * 64;
    const uint32_t ck0 = (uint32_t)(((0 * 2 + hb) ^ selA) * 16);   // kh=0
    const uint32_t ck1 = (uint32_t)(((1 * 2 + hb) ^ selA) * 16);   // kh=1

    int stage = 0;
    for (int k = 0; k < KT; k++) {
        const uint32_t st = sb + stage * STAGE_BYTES;
        const uint32_t sA  = st;
        const uint32_t sWh = st + TILE_S;
        const uint32_t sWl = st + 2 * TILE_S;

        // ---- phase 1: A16 x W16h ----
        uint32_t a16[2][2][4], wh[4][2][4];
        #pragma unroll
        for (int mi = 0; mi < 2; mi++) {
            ldsm4(a16[mi][0], sA + a_row_off + mi * 1024 + ck0);
            ldsm4(a16[mi][1], sA + a_row_off + mi * 1024 + ck1);
        }
        #pragma unroll
        for (int ni = 0; ni < 4; ni++) {
            ldsm4(wh[ni][0], sWh + w_row_off + ni * 1024 + ck0);
            ldsm4(wh[ni][1], sWh + w_row_off + ni * 1024 + ck1);
        }
        #pragma unroll
        for (int kh = 0; kh < 2; kh++)
            #pragma unroll
            for (int mi = 0; mi < 2; mi++)
                #pragma unroll
                for (int n8 = 0; n8 < 8; n8++)
                    mma_f16(acc[mi][n8], a16[mi][kh],
                            wh[n8 >> 1][kh][n8 & 1], wh[n8 >> 1][kh][2 + (n8 & 1)]);

        // ---- phase 2: A16 x W16l (reuse A fragments) ----
        uint32_t wl[4][2][4];
        #pragma unroll
        for (int ni = 0; ni < 4; ni++) {
            ldsm4(wl[ni][0], sWl + w_row_off + ni * 1024 + ck0);
            ldsm4(wl[ni][1], sWl + w_row_off + ni * 1024 + ck1);
        }
        #pragma unroll
        for (int kh = 0; kh < 2; kh++)
            #pragma unroll
            for (int mi = 0; mi < 2; mi++)
                #pragma unroll
                for (int n8 = 0; n8 < 8; n8++)
                    mma_f16(acc[mi][n8], a16[mi][kh],
                            wl[n8 >> 1][kh][n8 & 1], wl[n8 >> 1][kh][2 + (n8 & 1)]);

        // ---- issue next stage, advance pipeline (1 sync/iter) ----
        const int kn = k + NST - 1;
        if (kn < KT) {
            int sn = stage + NST - 1;
            if (sn >= NST) sn -= NST;
            load_stage(sn, kn);
        }
        CP_COMMIT();
        CP_WAIT(NST - 2);
        __syncthreads();
        if (++stage == NST) stage = 0;
    }

    // epilogue: fragment -> gmem (fp32)
    const int row0 = mt * BM + wm * 32 + (lane >> 2);
    const int col0 = nt * BN + wn * 64 + (lane & 3) * 2;
    #pragma unroll
    for (int mi = 0; mi < 2; mi++) {
        #pragma unroll
        for (int n8 = 0; n8 < 8; n8++) {
            float* p0 = C + (size_t)(row0 + mi * 16) * NDIM + col0 + n8 * 8;
            float* p1 = C + (size_t)(row0 + mi * 16 + 8) * NDIM + col0 + n8 * 8;
            p0[0] = acc[mi][n8][0];
            p0[1] = acc[mi][n8][1];
            p1[0] = acc[mi][n8][2];
            p1[1] = acc[mi][n8][3];
        }
    }
}

// ---------------------------------------------------------------------------
// Launch: convert -> dequant -> gemm  (graph-capturable, no allocs/syncs)
// Inputs (metadata order): x fp32, indices int32, codebook fp32, scales fp32
// ---------------------------------------------------------------------------
extern "C" void kernel_launch(void* const* d_in, const int* in_sizes, int n_in,
                              void* d_out, int out_size) {
    const float* x        = (const float*)d_in[0];
    const int*   indices  = (const int*)d_in[1];
    const float* codebook = (const float*)d_in[2];
    const float* scales   = (const float*)d_in[3];
    float* out = (float*)d_out;

    convert_x_kernel<<<(MDIM * (KDIM / 8) + 255) / 256, 256>>>(x);
    dequant_kernel<<<(NVEC + 255) / 256, 256>>>(indices, codebook, scales);

    cudaFuncSetAttribute(gemm_kernel, cudaFuncAttributeMaxDynamicSharedMemorySize,
                         SMEM_TOTAL);
    gemm_kernel<<<MT * NT, 256, SMEM_TOTAL>>>(out);
}

// round 11
// speedup vs baseline: 4.1466x; 1.8369x over previous
#include <cuda_runtime.h>
#include <cuda_fp16.h>
#include <cstdint>

// ---------------------------------------------------------------------------
// Problem constants
// ---------------------------------------------------------------------------
#define OUTF 4096
#define INF  11008
#define MDIM 4096                 // 2*2048 tokens
#define NDIM OUTF
#define KDIM INF
#define NVEC (OUTF * (INF / 8))   // 5,636,096 code vectors

// GEMM tiling
#define BM 128
#define BN 128
#define BK 32
#define KT (KDIM / BK)            // 344
#define MT (MDIM / BM)            // 32
#define NT (NDIM / BN)            // 32

#define TILE_G 8192               // packed gmem tile: 128 rows x 64B (linear)
#define TILE_S 8192               // smem tile: 128 rows x 64B (XOR-swizzled)
#define NST 6
#define STAGE_BYTES (2 * TILE_S)  // 16384 (A16, W16)
#define SMEM_TOTAL (NST * STAGE_BYTES)   // 98304 -> 2 CTAs/SM

// Packed fp16 operand tiles (static device arrays: alloc-guard safe)
__device__ __align__(256) uint8_t g_a16[(size_t)MT * KT * TILE_G];
__device__ __align__(256) uint8_t g_w16[(size_t)NT * KT * TILE_G];

// ---------------------------------------------------------------------------
// PTX helpers (plain sm_80+ — compile at compute_103)
// ---------------------------------------------------------------------------
__device__ __forceinline__ uint32_t smem_u32(const void* p) {
    uint32_t a;
    asm("{ .reg .u64 t; cvta.to.shared.u64 t, %1; cvt.u32.u64 %0, t; }"
        : "=r"(a) : "l"(p));
    return a;
}

__device__ __forceinline__ void cp_async16(uint32_t sdst, const void* gsrc) {
    asm volatile("cp.async.cg.shared.global [%0], [%1], 16;"
                 :: "r"(sdst), "l"(gsrc) : "memory");
}
#define CP_COMMIT()  asm volatile("cp.async.commit_group;" ::: "memory")
#define CP_WAIT(n)   asm volatile("cp.async.wait_group %0;" :: "n"(n) : "memory")

__device__ __forceinline__ void ldsm4(uint32_t (&r)[4], uint32_t addr) {
    asm volatile("ldmatrix.sync.aligned.m8n8.x4.shared.b16 {%0,%1,%2,%3}, [%4];"
                 : "=r"(r[0]), "=r"(r[1]), "=r"(r[2]), "=r"(r[3]) : "r"(addr));
}

__device__ __forceinline__ void mma_f16(float (&c)[4], const uint32_t (&a)[4],
                                        uint32_t b0, uint32_t b1) {
    asm volatile(
        "mma.sync.aligned.m16n8k16.row.col.f32.f16.f16.f32 "
        "{%0,%1,%2,%3}, {%4,%5,%6,%7}, {%8,%9}, {%0,%1,%2,%3};"
        : "+f"(c[0]), "+f"(c[1]), "+f"(c[2]), "+f"(c[3])
        : "r"(a[0]), "r"(a[1]), "r"(a[2]), "r"(a[3]), "r"(b0), "r"(b1));
}

// ---------------------------------------------------------------------------
// Kernel 1: x (fp32 row-major) -> packed A16 fp16 tiles (linear 128x64B)
// ---------------------------------------------------------------------------
__global__ void convert_x_kernel(const float* __restrict__ x) {
    int i = blockIdx.x * blockDim.x + threadIdx.x;    // one thread = 8 k-elems
    if (i >= MDIM * (KDIM / 8)) return;
    int m = i / (KDIM / 8);
    int k = (i % (KDIM / 8)) * 8;

    const float4* xp = reinterpret_cast<const float4*>(x + (size_t)m * KDIM + k);
    float4 v0 = xp[0], v1 = xp[1];
    float v[8] = {v0.x, v0.y, v0.z, v0.w, v1.x, v1.y, v1.z, v1.w};

    uint32_t h[4];
    #pragma unroll
    for (int e = 0; e < 4; e++) {
        __half h0 = __float2half_rn(v[2 * e]);
        __half h1 = __float2half_rn(v[2 * e + 1]);
        h[e] = (uint32_t)__half_as_ushort(h0) | ((uint32_t)__half_as_ushort(h1) << 16);
    }

    int mt = m >> 7, r = m & 127, kt = k >> 5, c = (k & 31) >> 3;
    size_t off = ((size_t)mt * KT + kt) * TILE_G + r * 64 + c * 16;
    *reinterpret_cast<uint4*>(g_a16 + off) = make_uint4(h[0], h[1], h[2], h[3]);
}

// ---------------------------------------------------------------------------
// Kernel 2: dequant -> packed W16 fp16 tiles (linear 128x64B)
// ---------------------------------------------------------------------------
__global__ void dequant_kernel(const int* __restrict__ indices,
                               const float* __restrict__ codebook,
                               const float* __restrict__ scales) {
    int i = blockIdx.x * blockDim.x + threadIdx.x;    // one thread = one 8-vector
    if (i >= NVEC) return;
    int n = i / (INF / 8);
    int k = (i % (INF / 8)) * 8;

    int code = indices[i];
    const float4* cb = reinterpret_cast<const float4*>(codebook) + (size_t)code * 2;
    float4 c0 = cb[0], c1 = cb[1];
    float s = __ldg(&scales[n]);
    float v[8] = {c0.x * s, c0.y * s, c0.z * s, c0.w * s,
                  c1.x * s, c1.y * s, c1.z * s, c1.w * s};

    uint32_t h[4];
    #pragma unroll
    for (int e = 0; e < 4; e++) {
        __half h0 = __float2half_rn(v[2 * e]);
        __half h1 = __float2half_rn(v[2 * e + 1]);
        h[e] = (uint32_t)__half_as_ushort(h0) | ((uint32_t)__half_as_ushort(h1) << 16);
    }

    int nt = n >> 7, r = n & 127, kt = k >> 5, c = (k & 31) >> 3;
    size_t off = ((size_t)nt * KT + kt) * TILE_G + r * 64 + c * 16;
    *reinterpret_cast<uint4*>(g_w16 + off) = make_uint4(h[0], h[1], h[2], h[3]);
}

// ---------------------------------------------------------------------------
// Kernel 3: fp16 HMMA GEMM  C = A16·W16ᵀ
// 128x128 CTA, BK=32, NST=6 cp.async pipeline, XOR-swizzled smem,
// 2 CTAs/SM, 1 syncthreads/iter
// smem swizzle: byte = row*64 + (c ^ ((row>>1)&3))*16
// ---------------------------------------------------------------------------
__global__ void __launch_bounds__(256, 2)
gemm_kernel(float* __restrict__ C) {
    extern __shared__ __align__(1024) uint8_t smem[];
    const uint32_t sb = smem_u32(smem);
    const int tid = threadIdx.x;
    const int lane = tid & 31;
    const int wid = tid >> 5;
    const int wm = wid & 3;       // 4 m-warps (32 rows each)
    const int wn = wid >> 2;      // 2 n-warps (64 cols each)

    // grouped raster: 8 m-tiles per group for L2 reuse
    const int bid = blockIdx.x;
    const int mt = (bid >> 8) * 8 + (bid & 7);
    const int nt = (bid >> 3) & 31;

    const uint8_t* gA = g_a16 + (size_t)mt * KT * TILE_G;
    const uint8_t* gW = g_w16 + (size_t)nt * KT * TILE_G;

    // cp.async mapping: 1024 chunks/stage, 4 per thread
    // ch = tid + j*256 : tile=ch>>9, row=(ch&511)>>2, c=ch&3 (swizzled dst)
    auto load_stage = [&](int s, int kt) {
        #pragma unroll
        for (int j = 0; j < 4; j++) {
            int ch = tid + j * 256;
            int row = (ch & 511) >> 2;
            int c = ch & 3;
            int cs = c ^ ((row >> 1) & 3);
            const uint8_t* gsrc = (ch < 512 ? gA : gW) + (size_t)kt * TILE_G
                                  + row * 64 + c * 16;
            uint32_t sdst = sb + s * STAGE_BYTES + (ch < 512 ? 0 : TILE_S)
                            + row * 64 + cs * 16;
            cp_async16(sdst, gsrc);
        }
    };

    // prologue: fill NST-1 stages
    #pragma unroll
    for (int s = 0; s < NST - 1; s++) {
        load_stage(s, s);
        CP_COMMIT();
    }
    CP_WAIT(NST - 2);
    __syncthreads();

    float acc[2][8][4];
    #pragma unroll
    for (int mi = 0; mi < 2; mi++)
        #pragma unroll
        for (int n8 = 0; n8 < 8; n8++)
            #pragma unroll
            for (int q = 0; q < 4; q++) acc[mi][n8][q] = 0.0f;

    // per-thread ldmatrix addressing (swizzle select constant per thread)
    const int hb = lane >> 4;                 // 16B half select
    const int rA = (lane & 15);
    const int selA = (rA >> 1) & 3;
    const uint32_t a_row_off = (uint32_t)(wm * 32 + rA) * 64;
    const uint32_t w_row_off = (uint32_t)(wn * 64 + rA) * 64;
    const uint32_t ck0 = (uint32_t)(((0 * 2 + hb) ^ selA) * 16);   // kh=0
    const uint32_t ck1 = (uint32_t)(((1 * 2 + hb) ^ selA) * 16);   // kh=1

    int stage = 0;
    for (int k = 0; k < KT; k++) {
        const uint32_t sA = sb + stage * STAGE_BYTES;
        const uint32_t sW = sA + TILE_S;

        uint32_t a16[2][2][4], wr[4][2][4];
        #pragma unroll
        for (int mi = 0; mi < 2; mi++) {
            ldsm4(a16[mi][0], sA + a_row_off + mi * 1024 + ck0);
            ldsm4(a16[mi][1], sA + a_row_off + mi * 1024 + ck1);
        }
        #pragma unroll
        for (int ni = 0; ni < 4; ni++) {
            ldsm4(wr[ni][0], sW + w_row_off + ni * 1024 + ck0);
            ldsm4(wr[ni][1], sW + w_row_off + ni * 1024 + ck1);
        }
        #pragma unroll
        for (int kh = 0; kh < 2; kh++)
            #pragma unroll
            for (int mi = 0; mi < 2; mi++)
                #pragma unroll
                for (int n8 = 0; n8 < 8; n8++)
                    mma_f16(acc[mi][n8], a16[mi][kh],
                            wr[n8 >> 1][kh][n8 & 1], wr[n8 >> 1][kh][2 + (n8 & 1)]);

        // issue next stage, advance pipeline (1 sync/iter)
        const int kn = k + NST - 1;
        if (kn < KT) {
            int sn = stage + NST - 1;
            if (sn >= NST) sn -= NST;
            load_stage(sn, kn);
        }
        CP_COMMIT();
        CP_WAIT(NST - 2);
        __syncthreads();
        if (++stage == NST) stage = 0;
    }

    // epilogue: fragment -> gmem (fp32)
    const int row0 = mt * BM + wm * 32 + (lane >> 2);
    const int col0 = nt * BN + wn * 64 + (lane & 3) * 2;
    #pragma unroll
    for (int mi = 0; mi < 2; mi++) {
        #pragma unroll
        for (int n8 = 0; n8 < 8; n8++) {
            float* p0 = C + (size_t)(row0 + mi * 16) * NDIM + col0 + n8 * 8;
            float* p1 = C + (size_t)(row0 + mi * 16 + 8) * NDIM + col0 + n8 * 8;
            p0[0] = acc[mi][n8][0];
            p0[1] = acc[mi][n8][1];
            p1[0] = acc[mi][n8][2];
            p1[1] = acc[mi][n8][3];
        }
    }
}

// ---------------------------------------------------------------------------
// Launch: convert -> dequant -> gemm  (graph-capturable, no allocs/syncs)
// Inputs (metadata order): x fp32, indices int32, codebook fp32, scales fp32
// ---------------------------------------------------------------------------
extern "C" void kernel_launch(void* const* d_in, const int* in_sizes, int n_in,
                              void* d_out, int out_size) {
    const float* x        = (const float*)d_in[0];
    const int*   indices  = (const int*)d_in[1];
    const float* codebook = (const float*)d_in[2];
    const float* scales   = (const float*)d_in[3];
    float* out = (float*)d_out;

    convert_x_kernel<<<(MDIM * (KDIM / 8) + 255) / 256, 256>>>(x);
    dequant_kernel<<<(NVEC + 255) / 256, 256>>>(indices, codebook, scales);

    cudaFuncSetAttribute(gemm_kernel, cudaFuncAttributeMaxDynamicSharedMemorySize,
                         SMEM_TOTAL);
    gemm_kernel<<<MT * NT, 256, SMEM_TOTAL>>>(out);
}

// round 12
// speedup vs baseline: 4.2958x; 1.0360x over previous
#include <cuda_runtime.h>
#include <cuda_fp16.h>
#include <cstdint>

// ---------------------------------------------------------------------------
// Problem constants
// ---------------------------------------------------------------------------
#define OUTF 4096
#define INF  11008
#define MDIM 4096                 // 2*2048 tokens
#define NDIM OUTF
#define KDIM INF
#define NVEC (OUTF * (INF / 8))   // 5,636,096 code vectors

// GEMM tiling
#define BM 128
#define BN 128
#define BK 32                     // packing granularity (per gmem tile)
#define KT (KDIM / BK)            // 344 packed k-tiles
#define KIT (KT / 2)              // 172 mainloop iterations (64-k per stage)
#define MT (MDIM / BM)            // 32
#define NT (NDIM / BN)            // 32

#define TILE_G 8192               // packed gmem tile: 128 rows x 64B (linear)
#define TILE_S 8192               // smem tile: 128 rows x 64B (XOR-swizzled)
#define NST 3
#define STAGE_BYTES (4 * TILE_S)  // 32768 (A0, A1, W0, W1 — two k-tiles)
#define SMEM_TOTAL (NST * STAGE_BYTES)   // 98304 -> 2 CTAs/SM

// Packed fp16 operand tiles (static device arrays: alloc-guard safe)
__device__ __align__(256) uint8_t g_a16[(size_t)MT * KT * TILE_G];
__device__ __align__(256) uint8_t g_w16[(size_t)NT * KT * TILE_G];

// ---------------------------------------------------------------------------
// PTX helpers (plain sm_80+ — compile at compute_103)
// ---------------------------------------------------------------------------
__device__ __forceinline__ uint32_t smem_u32(const void* p) {
    uint32_t a;
    asm("{ .reg .u64 t; cvta.to.shared.u64 t, %1; cvt.u32.u64 %0, t; }"
        : "=r"(a) : "l"(p));
    return a;
}

__device__ __forceinline__ void cp_async16(uint32_t sdst, const void* gsrc) {
    asm volatile("cp.async.cg.shared.global [%0], [%1], 16;"
                 :: "r"(sdst), "l"(gsrc) : "memory");
}
#define CP_COMMIT()  asm volatile("cp.async.commit_group;" ::: "memory")
#define CP_WAIT(n)   asm volatile("cp.async.wait_group %0;" :: "n"(n) : "memory")

__device__ __forceinline__ void ldsm4(uint32_t (&r)[4], uint32_t addr) {
    asm volatile("ldmatrix.sync.aligned.m8n8.x4.shared.b16 {%0,%1,%2,%3}, [%4];"
                 : "=r"(r[0]), "=r"(r[1]), "=r"(r[2]), "=r"(r[3]) : "r"(addr));
}

__device__ __forceinline__ void mma_f16(float (&c)[4], const uint32_t (&a)[4],
                                        uint32_t b0, uint32_t b1) {
    asm volatile(
        "mma.sync.aligned.m16n8k16.row.col.f32.f16.f16.f32 "
        "{%0,%1,%2,%3}, {%4,%5,%6,%7}, {%8,%9}, {%0,%1,%2,%3};"
        : "+f"(c[0]), "+f"(c[1]), "+f"(c[2]), "+f"(c[3])
        : "r"(a[0]), "r"(a[1]), "r"(a[2]), "r"(a[3]), "r"(b0), "r"(b1));
}

// ---------------------------------------------------------------------------
// Kernel 1: x (fp32 row-major) -> packed A16 fp16 tiles (linear 128x64B)
// ---------------------------------------------------------------------------
__global__ void convert_x_kernel(const float* __restrict__ x) {
    int i = blockIdx.x * blockDim.x + threadIdx.x;    // one thread = 8 k-elems
    if (i >= MDIM * (KDIM / 8)) return;
    int m = i / (KDIM / 8);
    int k = (i % (KDIM / 8)) * 8;

    const float4* xp = reinterpret_cast<const float4*>(x + (size_t)m * KDIM + k);
    float4 v0 = xp[0], v1 = xp[1];
    float v[8] = {v0.x, v0.y, v0.z, v0.w, v1.x, v1.y, v1.z, v1.w};

    uint32_t h[4];
    #pragma unroll
    for (int e = 0; e < 4; e++) {
        __half h0 = __float2half_rn(v[2 * e]);
        __half h1 = __float2half_rn(v[2 * e + 1]);
        h[e] = (uint32_t)__half_as_ushort(h0) | ((uint32_t)__half_as_ushort(h1) << 16);
    }

    int mt = m >> 7, r = m & 127, kt = k >> 5, c = (k & 31) >> 3;
    size_t off = ((size_t)mt * KT + kt) * TILE_G + r * 64 + c * 16;
    *reinterpret_cast<uint4*>(g_a16 + off) = make_uint4(h[0], h[1], h[2], h[3]);
}

// ---------------------------------------------------------------------------
// Kernel 2: dequant -> packed W16 fp16 tiles (linear 128x64B)
// ---------------------------------------------------------------------------
__global__ void dequant_kernel(const int* __restrict__ indices,
                               const float* __restrict__ codebook,
                               const float* __restrict__ scales) {
    int i = blockIdx.x * blockDim.x + threadIdx.x;    // one thread = one 8-vector
    if (i >= NVEC) return;
    int n = i / (INF / 8);
    int k = (i % (INF / 8)) * 8;

    int code = indices[i];
    const float4* cb = reinterpret_cast<const float4*>(codebook) + (size_t)code * 2;
    float4 c0 = cb[0], c1 = cb[1];
    float s = __ldg(&scales[n]);
    float v[8] = {c0.x * s, c0.y * s, c0.z * s, c0.w * s,
                  c1.x * s, c1.y * s, c1.z * s, c1.w * s};

    uint32_t h[4];
    #pragma unroll
    for (int e = 0; e < 4; e++) {
        __half h0 = __float2half_rn(v[2 * e]);
        __half h1 = __float2half_rn(v[2 * e + 1]);
        h[e] = (uint32_t)__half_as_ushort(h0) | ((uint32_t)__half_as_ushort(h1) << 16);
    }

    int nt = n >> 7, r = n & 127, kt = k >> 5, c = (k & 31) >> 3;
    size_t off = ((size_t)nt * KT + kt) * TILE_G + r * 64 + c * 16;
    *reinterpret_cast<uint4*>(g_w16 + off) = make_uint4(h[0], h[1], h[2], h[3]);
}

// ---------------------------------------------------------------------------
// Kernel 3: fp16 HMMA GEMM  C = A16·W16ᵀ
// 128x128 CTA, 64-k pipeline stages (two 32-k sub-steps), NST=3,
// XOR-swizzled smem, 2 CTAs/SM, ONE wait+sync per 64-k.
// Next-stage cp.async issued between the two sub-step MMA blocks.
// smem swizzle: byte = row*64 + (c ^ ((row>>1)&3))*16
// ---------------------------------------------------------------------------
__global__ void __launch_bounds__(256, 2)
gemm_kernel(float* __restrict__ C) {
    extern __shared__ __align__(1024) uint8_t smem[];
    const uint32_t sb = smem_u32(smem);
    const int tid = threadIdx.x;
    const int lane = tid & 31;
    const int wid = tid >> 5;
    const int wm = wid & 3;       // 4 m-warps (32 rows each)
    const int wn = wid >> 2;      // 2 n-warps (64 cols each)

    // grouped raster: 8 m-tiles per group for L2 reuse
    const int bid = blockIdx.x;
    const int mt = (bid >> 8) * 8 + (bid & 7);
    const int nt = (bid >> 3) & 31;

    const uint8_t* gA = g_a16 + (size_t)mt * KT * TILE_G;
    const uint8_t* gW = g_w16 + (size_t)nt * KT * TILE_G;

    // stage layout: [A(2k) | A(2k+1) | W(2k) | W(2k+1)], 8KB each.
    // cp.async: 2048 chunks/stage, 8 per thread. ch -> quadrant=ch>>9.
    auto load_stage = [&](int s, int it) {
        #pragma unroll
        for (int j = 0; j < 8; j++) {
            int ch = tid + j * 256;
            int quad = ch >> 9;              // 0:A0 1:A1 2:W0 3:W1
            int row = (ch & 511) >> 2;
            int c = ch & 3;
            int cs = c ^ ((row >> 1) & 3);
            int ktile = 2 * it + (quad & 1);
            const uint8_t* gsrc = ((quad < 2) ? gA : gW) + (size_t)ktile * TILE_G
                                  + row * 64 + c * 16;
            uint32_t sdst = sb + s * STAGE_BYTES + quad * TILE_S
                            + row * 64 + cs * 16;
            cp_async16(sdst, gsrc);
        }
    };

    // prologue: fill NST-1 stages
    #pragma unroll
    for (int s = 0; s < NST - 1; s++) {
        load_stage(s, s);
        CP_COMMIT();
    }
    CP_WAIT(NST - 2);
    __syncthreads();

    float acc[2][8][4];
    #pragma unroll
    for (int mi = 0; mi < 2; mi++)
        #pragma unroll
        for (int n8 = 0; n8 < 8; n8++)
            #pragma unroll
            for (int q = 0; q < 4; q++) acc[mi][n8][q] = 0.0f;

    // per-thread ldmatrix addressing (swizzle select constant per thread)
    const int hb = lane >> 4;                 // 16B half select
    const int rA = (lane & 15);
    const int selA = (rA >> 1) & 3;
    const uint32_t a_row_off = (uint32_t)(wm * 32 + rA) * 64;
    const uint32_t w_row_off = (uint32_t)(wn * 64 + rA) * 64;
    const uint32_t ck0 = (uint32_t)(((0 * 2 + hb) ^ selA) * 16);   // kh=0
    const uint32_t ck1 = (uint32_t)(((1 * 2 + hb) ^ selA) * 16);   // kh=1

    int stage = 0;
    for (int it = 0; it < KIT; it++) {
        const uint32_t st = sb + stage * STAGE_BYTES;

        // ---- sub-step 0 (k-tile 2*it) ----
        {
            const uint32_t sA = st;
            const uint32_t sW = st + 2 * TILE_S;
            uint32_t a16[2][2][4], wr[4][2][4];
            #pragma unroll
            for (int mi = 0; mi < 2; mi++) {
                ldsm4(a16[mi][0], sA + a_row_off + mi * 1024 + ck0);
                ldsm4(a16[mi][1], sA + a_row_off + mi * 1024 + ck1);
            }
            #pragma unroll
            for (int ni = 0; ni < 4; ni++) {
                ldsm4(wr[ni][0], sW + w_row_off + ni * 1024 + ck0);
                ldsm4(wr[ni][1], sW + w_row_off + ni * 1024 + ck1);
            }
            #pragma unroll
            for (int kh = 0; kh < 2; kh++)
                #pragma unroll
                for (int mi = 0; mi < 2; mi++)
                    #pragma unroll
                    for (int n8 = 0; n8 < 8; n8++)
                        mma_f16(acc[mi][n8], a16[mi][kh],
                                wr[n8 >> 1][kh][n8 & 1], wr[n8 >> 1][kh][2 + (n8 & 1)]);
        }

        // ---- issue next stage mid-iteration (drains behind sub-step 1) ----
        const int in_ = it + NST - 1;
        if (in_ < KIT) {
            int sn = stage + NST - 1;
            if (sn >= NST) sn -= NST;
            load_stage(sn, in_);
        }
        CP_COMMIT();

        // ---- sub-step 1 (k-tile 2*it+1) ----
        {
            const uint32_t sA = st + TILE_S;
            const uint32_t sW = st + 3 * TILE_S;
            uint32_t a16[2][2][4], wr[4][2][4];
            #pragma unroll
            for (int mi = 0; mi < 2; mi++) {
                ldsm4(a16[mi][0], sA + a_row_off + mi * 1024 + ck0);
                ldsm4(a16[mi][1], sA + a_row_off + mi * 1024 + ck1);
            }
            #pragma unroll
            for (int ni = 0; ni < 4; ni++) {
                ldsm4(wr[ni][0], sW + w_row_off + ni * 1024 + ck0);
                ldsm4(wr[ni][1], sW + w_row_off + ni * 1024 + ck1);
            }
            #pragma unroll
            for (int kh = 0; kh < 2; kh++)
                #pragma unroll
                for (int mi = 0; mi < 2; mi++)
                    #pragma unroll
                    for (int n8 = 0; n8 < 8; n8++)
                        mma_f16(acc[mi][n8], a16[mi][kh],
                                wr[n8 >> 1][kh][n8 & 1], wr[n8 >> 1][kh][2 + (n8 & 1)]);
        }

        // ---- advance pipeline (ONE wait+sync per 64-k) ----
        CP_WAIT(NST - 2);
        __syncthreads();
        if (++stage == NST) stage = 0;
    }

    // epilogue: fragment -> gmem (fp32)
    const int row0 = mt * BM + wm * 32 + (lane >> 2);
    const int col0 = nt * BN + wn * 64 + (lane & 3) * 2;
    #pragma unroll
    for (int mi = 0; mi < 2; mi++) {
        #pragma unroll
        for (int n8 = 0; n8 < 8; n8++) {
            float* p0 = C + (size_t)(row0 + mi * 16) * NDIM + col0 + n8 * 8;
            float* p1 = C + (size_t)(row0 + mi * 16 + 8) * NDIM + col0 + n8 * 8;
            p0[0] = acc[mi][n8][0];
            p0[1] = acc[mi][n8][1];
            p1[0] = acc[mi][n8][2];
            p1[1] = acc[mi][n8][3];
        }
    }
}

// ---------------------------------------------------------------------------
// Launch: convert -> dequant -> gemm  (graph-capturable, no allocs/syncs)
// Inputs (metadata order): x fp32, indices int32, codebook fp32, scales fp32
// ---------------------------------------------------------------------------
extern "C" void kernel_launch(void* const* d_in, const int* in_sizes, int n_in,
                              void* d_out, int out_size) {
    const float* x        = (const float*)d_in[0];
    const int*   indices  = (const int*)d_in[1];
    const float* codebook = (const float*)d_in[2];
    const float* scales   = (const float*)d_in[3];
    float* out = (float*)d_out;

    convert_x_kernel<<<(MDIM * (KDIM / 8) + 255) / 256, 256>>>(x);
    dequant_kernel<<<(NVEC + 255) / 256, 256>>>(indices, codebook, scales);

    cudaFuncSetAttribute(gemm_kernel, cudaFuncAttributeMaxDynamicSharedMemorySize,
                         SMEM_TOTAL);
    gemm_kernel<<<MT * NT, 256, SMEM_TOTAL>>>(out);
}

// round 13
// speedup vs baseline: 4.3317x; 1.0084x over previous
#include <cuda_runtime.h>
#include <cuda_fp16.h>
#include <cstdint>

// ---------------------------------------------------------------------------
// Problem constants
// ---------------------------------------------------------------------------
#define OUTF 4096
#define INF  11008
#define MDIM 4096                 // 2*2048 tokens
#define NDIM OUTF
#define KDIM INF
#define NVEC (OUTF * (INF / 8))   // 5,636,096 code vectors

// GEMM tiling
#define BM 128
#define BN 128
#define BK 32                     // packing granularity (per gmem tile)
#define KT (KDIM / BK)            // 344 packed k-tiles
#define KIT (KT / 2)              // 172 mainloop iterations (64-k per stage)
#define MT (MDIM / BM)            // 32
#define NT (NDIM / BN)            // 32

#define TILE_G 8192               // packed gmem tile: 128 rows x 64B (linear)
#define TILE_S 8192               // smem tile: 128 rows x 64B (XOR-swizzled)
#define NST 3
#define STAGE_BYTES (4 * TILE_S)  // 32768 (A0, A1, W0, W1 — two k-tiles)
#define SMEM_TOTAL (NST * STAGE_BYTES)   // 98304 -> 2 CTAs/SM

// Packed fp16 operand tiles (static device arrays: alloc-guard safe)
__device__ __align__(256) uint8_t g_a16[(size_t)MT * KT * TILE_G];
__device__ __align__(256) uint8_t g_w16[(size_t)NT * KT * TILE_G];

// ---------------------------------------------------------------------------
// PTX helpers (plain sm_80+ — compile at compute_103)
// ---------------------------------------------------------------------------
__device__ __forceinline__ uint32_t smem_u32(const void* p) {
    uint32_t a;
    asm("{ .reg .u64 t; cvta.to.shared.u64 t, %1; cvt.u32.u64 %0, t; }"
        : "=r"(a) : "l"(p));
    return a;
}

__device__ __forceinline__ void cp_async16(uint32_t sdst, const void* gsrc) {
    asm volatile("cp.async.cg.shared.global [%0], [%1], 16;"
                 :: "r"(sdst), "l"(gsrc) : "memory");
}
#define CP_COMMIT()  asm volatile("cp.async.commit_group;" ::: "memory")
#define CP_WAIT(n)   asm volatile("cp.async.wait_group %0;" :: "n"(n) : "memory")

__device__ __forceinline__ void ldsm4(uint32_t (&r)[4], uint32_t addr) {
    asm volatile("ldmatrix.sync.aligned.m8n8.x4.shared.b16 {%0,%1,%2,%3}, [%4];"
                 : "=r"(r[0]), "=r"(r[1]), "=r"(r[2]), "=r"(r[3]) : "r"(addr));
}

__device__ __forceinline__ void mma_f16(float (&c)[4], const uint32_t (&a)[4],
                                        uint32_t b0, uint32_t b1) {
    asm volatile(
        "mma.sync.aligned.m16n8k16.row.col.f32.f16.f16.f32 "
        "{%0,%1,%2,%3}, {%4,%5,%6,%7}, {%8,%9}, {%0,%1,%2,%3};"
        : "+f"(c[0]), "+f"(c[1]), "+f"(c[2]), "+f"(c[3])
        : "r"(a[0]), "r"(a[1]), "r"(a[2]), "r"(a[3]), "r"(b0), "r"(b1));
}

// ---------------------------------------------------------------------------
// Kernel 1: x (fp32 row-major) -> packed A16 fp16 tiles (linear 128x64B)
// ---------------------------------------------------------------------------
__global__ void convert_x_kernel(const float* __restrict__ x) {
    int i = blockIdx.x * blockDim.x + threadIdx.x;    // one thread = 8 k-elems
    if (i >= MDIM * (KDIM / 8)) return;
    int m = i / (KDIM / 8);
    int k = (i % (KDIM / 8)) * 8;

    const float4* xp = reinterpret_cast<const float4*>(x + (size_t)m * KDIM + k);
    float4 v0 = xp[0], v1 = xp[1];
    float v[8] = {v0.x, v0.y, v0.z, v0.w, v1.x, v1.y, v1.z, v1.w};

    uint32_t h[4];
    #pragma unroll
    for (int e = 0; e < 4; e++) {
        __half h0 = __float2half_rn(v[2 * e]);
        __half h1 = __float2half_rn(v[2 * e + 1]);
        h[e] = (uint32_t)__half_as_ushort(h0) | ((uint32_t)__half_as_ushort(h1) << 16);
    }

    int mt = m >> 7, r = m & 127, kt = k >> 5, c = (k & 31) >> 3;
    size_t off = ((size_t)mt * KT + kt) * TILE_G + r * 64 + c * 16;
    *reinterpret_cast<uint4*>(g_a16 + off) = make_uint4(h[0], h[1], h[2], h[3]);
}

// ---------------------------------------------------------------------------
// Kernel 2: dequant -> packed W16 fp16 tiles (linear 128x64B)
// ---------------------------------------------------------------------------
__global__ void dequant_kernel(const int* __restrict__ indices,
                               const float* __restrict__ codebook,
                               const float* __restrict__ scales) {
    int i = blockIdx.x * blockDim.x + threadIdx.x;    // one thread = one 8-vector
    if (i >= NVEC) return;
    int n = i / (INF / 8);
    int k = (i % (INF / 8)) * 8;

    int code = indices[i];
    const float4* cb = reinterpret_cast<const float4*>(codebook) + (size_t)code * 2;
    float4 c0 = cb[0], c1 = cb[1];
    float s = __ldg(&scales[n]);
    float v[8] = {c0.x * s, c0.y * s, c0.z * s, c0.w * s,
                  c1.x * s, c1.y * s, c1.z * s, c1.w * s};

    uint32_t h[4];
    #pragma unroll
    for (int e = 0; e < 4; e++) {
        __half h0 = __float2half_rn(v[2 * e]);
        __half h1 = __float2half_rn(v[2 * e + 1]);
        h[e] = (uint32_t)__half_as_ushort(h0) | ((uint32_t)__half_as_ushort(h1) << 16);
    }

    int nt = n >> 7, r = n & 127, kt = k >> 5, c = (k & 31) >> 3;
    size_t off = ((size_t)nt * KT + kt) * TILE_G + r * 64 + c * 16;
    *reinterpret_cast<uint4*>(g_w16 + off) = make_uint4(h[0], h[1], h[2], h[3]);
}

// ---------------------------------------------------------------------------
// Kernel 3: fp16 HMMA GEMM  C = A16·W16ᵀ
// 128x128 CTA, 64-k pipeline stages (two 32-k sub-steps), NST=3,
// XOR-swizzled smem, 2 CTAs/SM, one wait+sync per 64-k.
// Sub-step body interleaves W-ldsm with the MMAs that consume them so the
// LDS crossbar and tensor pipe overlap within each warp.
// smem swizzle: byte = row*64 + (c ^ ((row>>1)&3))*16
// ---------------------------------------------------------------------------
__global__ void __launch_bounds__(256, 2)
gemm_kernel(float* __restrict__ C) {
    extern __shared__ __align__(1024) uint8_t smem[];
    const uint32_t sb = smem_u32(smem);
    const int tid = threadIdx.x;
    const int lane = tid & 31;
    const int wid = tid >> 5;
    const int wm = wid & 3;       // 4 m-warps (32 rows each)
    const int wn = wid >> 2;      // 2 n-warps (64 cols each)

    // grouped raster: 8 m-tiles per group for L2 reuse
    const int bid = blockIdx.x;
    const int mt = (bid >> 8) * 8 + (bid & 7);
    const int nt = (bid >> 3) & 31;

    const uint8_t* gA = g_a16 + (size_t)mt * KT * TILE_G;
    const uint8_t* gW = g_w16 + (size_t)nt * KT * TILE_G;

    // stage layout: [A(2k) | A(2k+1) | W(2k) | W(2k+1)], 8KB each.
    // cp.async: 2048 chunks/stage, 8 per thread. ch -> quadrant=ch>>9.
    auto load_stage = [&](int s, int it) {
        #pragma unroll
        for (int j = 0; j < 8; j++) {
            int ch = tid + j * 256;
            int quad = ch >> 9;              // 0:A0 1:A1 2:W0 3:W1
            int row = (ch & 511) >> 2;
            int c = ch & 3;
            int cs = c ^ ((row >> 1) & 3);
            int ktile = 2 * it + (quad & 1);
            const uint8_t* gsrc = ((quad < 2) ? gA : gW) + (size_t)ktile * TILE_G
                                  + row * 64 + c * 16;
            uint32_t sdst = sb + s * STAGE_BYTES + quad * TILE_S
                            + row * 64 + cs * 16;
            cp_async16(sdst, gsrc);
        }
    };

    // prologue: fill NST-1 stages
    #pragma unroll
    for (int s = 0; s < NST - 1; s++) {
        load_stage(s, s);
        CP_COMMIT();
    }
    CP_WAIT(NST - 2);
    __syncthreads();

    float acc[2][8][4];
    #pragma unroll
    for (int mi = 0; mi < 2; mi++)
        #pragma unroll
        for (int n8 = 0; n8 < 8; n8++)
            #pragma unroll
            for (int q = 0; q < 4; q++) acc[mi][n8][q] = 0.0f;

    // per-thread ldmatrix addressing (swizzle select constant per thread)
    const int hb = lane >> 4;                 // 16B half select
    const int rA = (lane & 15);
    const int selA = (rA >> 1) & 3;
    const uint32_t a_row_off = (uint32_t)(wm * 32 + rA) * 64;
    const uint32_t w_row_off = (uint32_t)(wn * 64 + rA) * 64;
    const uint32_t ck0 = (uint32_t)(((0 * 2 + hb) ^ selA) * 16);   // kh=0
    const uint32_t ck1 = (uint32_t)(((1 * 2 + hb) ^ selA) * 16);   // kh=1

    // interleaved sub-step: A ldsm burst, then per-ni (W ldsm -> 8 MMAs)
    auto sub_step = [&](uint32_t sA, uint32_t sW) {
        uint32_t a16[2][2][4], wr[4][2][4];
        #pragma unroll
        for (int mi = 0; mi < 2; mi++) {
            ldsm4(a16[mi][0], sA + a_row_off + mi * 1024 + ck0);
            ldsm4(a16[mi][1], sA + a_row_off + mi * 1024 + ck1);
        }
        #pragma unroll
        for (int ni = 0; ni < 4; ni++) {
            ldsm4(wr[ni][0], sW + w_row_off + ni * 1024 + ck0);
            ldsm4(wr[ni][1], sW + w_row_off + ni * 1024 + ck1);
            #pragma unroll
            for (int kh = 0; kh < 2; kh++)
                #pragma unroll
                for (int mi = 0; mi < 2; mi++)
                    #pragma unroll
                    for (int j = 0; j < 2; j++)
                        mma_f16(acc[mi][2 * ni + j], a16[mi][kh],
                                wr[ni][kh][j], wr[ni][kh][2 + j]);
        }
    };

    int stage = 0;
    for (int it = 0; it < KIT; it++) {
        const uint32_t st = sb + stage * STAGE_BYTES;

        // ---- sub-step 0 (k-tile 2*it) ----
        sub_step(st, st + 2 * TILE_S);

        // ---- issue next stage mid-iteration (drains behind sub-step 1) ----
        const int in_ = it + NST - 1;
        if (in_ < KIT) {
            int sn = stage + NST - 1;
            if (sn >= NST) sn -= NST;
            load_stage(sn, in_);
        }
        CP_COMMIT();

        // ---- sub-step 1 (k-tile 2*it+1) ----
        sub_step(st + TILE_S, st + 3 * TILE_S);

        // ---- advance pipeline (one wait+sync per 64-k) ----
        CP_WAIT(NST - 2);
        __syncthreads();
        if (++stage == NST) stage = 0;
    }

    // epilogue: fragment -> gmem (fp32)
    const int row0 = mt * BM + wm * 32 + (lane >> 2);
    const int col0 = nt * BN + wn * 64 + (lane & 3) * 2;
    #pragma unroll
    for (int mi = 0; mi < 2; mi++) {
        #pragma unroll
        for (int n8 = 0; n8 < 8; n8++) {
            float* p0 = C + (size_t)(row0 + mi * 16) * NDIM + col0 + n8 * 8;
            float* p1 = C + (size_t)(row0 + mi * 16 + 8) * NDIM + col0 + n8 * 8;
            p0[0] = acc[mi][n8][0];
            p0[1] = acc[mi][n8][1];
            p1[0] = acc[mi][n8][2];
            p1[1] = acc[mi][n8][3];
        }
    }
}

// ---------------------------------------------------------------------------
// Launch: convert -> dequant -> gemm  (graph-capturable, no allocs/syncs)
// Inputs (metadata order): x fp32, indices int32, codebook fp32, scales fp32
// ---------------------------------------------------------------------------
extern "C" void kernel_launch(void* const* d_in, const int* in_sizes, int n_in,
                              void* d_out, int out_size) {
    const float* x        = (const float*)d_in[0];
    const int*   indices  = (const int*)d_in[1];
    const float* codebook = (const float*)d_in[2];
    const float* scales   = (const float*)d_in[3];
    float* out = (float*)d_out;

    convert_x_kernel<<<(MDIM * (KDIM / 8) + 255) / 256, 256>>>(x);
    dequant_kernel<<<(NVEC + 255) / 256, 256>>>(indices, codebook, scales);

    cudaFuncSetAttribute(gemm_kernel, cudaFuncAttributeMaxDynamicSharedMemorySize,
                         SMEM_TOTAL);
    gemm_kernel<<<MT * NT, 256, SMEM_TOTAL>>>(out);
}